// round 14
// baseline (speedup 1.0000x reference)
#include <cuda_runtime.h>
#include <cuda_bf16.h>
#include <cuda_fp16.h>
#include <mma.h>
#include <math.h>
#include <stdint.h>

using namespace nvcuda;

// ---------------- static scratch ----------------
__device__ __half g_Hh[140000 * 128];   // HS tables (half): t0@0 t1@50k t2@80k t3@130k
__device__ __half g_G2h[250000 * 128];  // per-edge continuous gate (t2), half
__device__ float g_ACC[115000 * 128];   // per-type NORMALIZED acc
__device__ float g_GTAB[80 * 128];      // categorical gate table
__device__ float g_GTA0[80 * 128];      // gate table * attn0
__device__ float g_AS[2 * 50000 * 4];   // per-src attn dots (t1 @0, t3 @200000)
__device__ float g_AD[4 * 50000 * 4];   // per-dst attn dots, per edge type
__device__ float g_WA[4 * 128 * 4];     // Wdst collapsed with attn
__device__ float g_BA[4 * 4];
__device__ __nv_bfloat16 g_WTh[8 * 16384]; // weights [k][n] row-major, bf16 hi
__device__ __nv_bfloat16 g_WTl[8 * 16384]; // weights [k][n] row-major, bf16 lo
// CSR scratch
__device__ int g_CNT[115008];
__device__ int g_OFF[115008];
__device__ int g_CUR[115008];
__device__ int g_BSUM[128];
__device__ int2 g_ELIST[1500000];       // (edge, src)

__device__ __forceinline__ float4 ld_half4(const __half* p) {
    uint2 u = *(const uint2*)p;
    __half2 a = *(__half2*)&u.x, b = *(__half2*)&u.y;
    float2 fa = __half22float2(a), fb = __half22float2(b);
    return make_float4(fa.x, fa.y, fb.x, fb.y);
}
__device__ __forceinline__ void st_half4(__half* p, float4 v) {
    __half2 a = __floats2half2_rn(v.x, v.y);
    __half2 b = __floats2half2_rn(v.z, v.w);
    uint2 u;
    u.x = *(uint32_t*)&a; u.y = *(uint32_t*)&b;
    *(uint2*)p = u;
}

__device__ __forceinline__ uint2 pack_part(float4 v, int lo) {
    __nv_bfloat16 hx = __float2bfloat16(v.x), hy = __float2bfloat16(v.y);
    __nv_bfloat16 hz = __float2bfloat16(v.z), hw = __float2bfloat16(v.w);
    if (lo) {
        hx = __float2bfloat16(v.x - __bfloat162float(hx));
        hy = __float2bfloat16(v.y - __bfloat162float(hy));
        hz = __float2bfloat16(v.z - __bfloat162float(hz));
        hw = __float2bfloat16(v.w - __bfloat162float(hw));
    }
    uint2 u;
    u.x = ((uint32_t)__bfloat16_as_ushort(hy) << 16) | __bfloat16_as_ushort(hx);
    u.y = ((uint32_t)__bfloat16_as_ushort(hw) << 16) | __bfloat16_as_ushort(hz);
    return u;
}

#define LDM 136
#define DYN_SMEM (3 * 128 * LDM * 2)    // A, Bh, Bl = 104448 B -> 2 blocks/SM

// ---------------- weight prep ----------------
struct WList { const float* w[8]; };
__global__ void prep_w(WList wl) {
    int m = blockIdx.x;
    int idx = blockIdx.y * 256 + threadIdx.x;
    float v = wl.w[m][idx];
    __nv_bfloat16 h = __float2bfloat16(v);
    g_WTh[m * 16384 + idx] = h;
    g_WTl[m * 16384 + idx] = __float2bfloat16(v - __bfloat162float(h));
}

__global__ void prep_wa(const float* __restrict__ Wdst, const float* __restrict__ bdst,
                        const float* __restrict__ attn) {
    int t = blockIdx.x, k = threadIdx.x;
    const float* W = Wdst + t * 16384;
    const float* at = attn + t * 128;
    float4 o;
    float* po = &o.x;
#pragma unroll
    for (int h = 0; h < 4; h++) {
        float s = 0.f;
        for (int dh = 0; dh < 32; dh++) s = fmaf(W[k * 128 + h * 32 + dh], at[h * 32 + dh], s);
        po[h] = s;
    }
    ((float4*)(g_WA + t * 512))[k] = o;
    if (k < 4) {
        const float* b = bdst + t * 128;
        float s = 0.f;
        for (int dh = 0; dh < 32; dh++) s = fmaf(b[k * 32 + dh], at[k * 32 + dh], s);
        g_BA[t * 4 + k] = s;
    }
}

__global__ void gtabk(const float* __restrict__ te, const float* __restrict__ se,
                      const float* __restrict__ Wg, const float* __restrict__ bg,
                      const float* __restrict__ attn0) {
    int c = threadIdx.x, r = blockIdx.x;
    int a = r >> 3, b = r & 7;
    float s = bg[c];
#pragma unroll 8
    for (int j = 0; j < 32; j++) s = fmaf(te[a * 32 + j], Wg[j * 128 + c], s);
#pragma unroll 8
    for (int j = 0; j < 32; j++) s = fmaf(se[b * 32 + j], Wg[(32 + j) * 128 + c], s);
    float g = 1.f / (1.f + expf(-s));
    g_GTAB[r * 128 + c] = g;
    g_GTA0[r * 128 + c] = g * attn0[c];
}

// ---------------- CSR build ----------------
struct EIdx { const int* dst[4]; const int* src[4]; int E[4]; int bofs[4]; int cbase[4]; };

__global__ void histK(EIdx P) {
    int b = blockIdx.x, t = 0;
    while (t + 1 < 4 && b >= P.bofs[t + 1]) t++;
    int e = (b - P.bofs[t]) * 256 + threadIdx.x;
    if (e >= P.E[t]) return;
    atomicAdd(&g_CNT[P.cbase[t] + P.dst[t][e]], 1);
}

__global__ void scanA(int N) {
    int base = blockIdx.x * 1024;
    int tid = threadIdx.x, lane = tid & 31, wid = tid >> 5;
    int v[4];
#pragma unroll
    for (int k = 0; k < 4; k++) {
        int i = base + tid * 4 + k;
        v[k] = (i < N) ? g_CNT[i] : 0;
    }
    int tsum = v[0] + v[1] + v[2] + v[3];
    int x = tsum;
#pragma unroll
    for (int o = 1; o < 32; o <<= 1) {
        int y = __shfl_up_sync(0xffffffffu, x, o);
        if (lane >= o) x += y;
    }
    __shared__ int ws[8];
    if (lane == 31) ws[wid] = x;
    __syncthreads();
    if (tid == 0) {
        int a = 0;
        for (int w = 0; w < 8; w++) { int tt = ws[w]; ws[w] = a; a += tt; }
        g_BSUM[blockIdx.x] = a;
    }
    __syncthreads();
    int run = x - tsum + ws[wid];
#pragma unroll
    for (int k = 0; k < 4; k++) {
        int i = base + tid * 4 + k;
        if (i < N) g_OFF[i] = run;
        run += v[k];
    }
}

__global__ void scanB(int nb) {
    int tid = threadIdx.x, lane = tid & 31, wid = tid >> 5;
    int v = (tid < nb) ? g_BSUM[tid] : 0;
    int x = v;
#pragma unroll
    for (int o = 1; o < 32; o <<= 1) {
        int y = __shfl_up_sync(0xffffffffu, x, o);
        if (lane >= o) x += y;
    }
    __shared__ int ws[4];
    if (lane == 31) ws[wid] = x;
    __syncthreads();
    int add = 0;
    for (int w = 0; w < wid; w++) add += ws[w];
    if (tid < nb) g_BSUM[tid] = x - v + add;
}

__global__ void scanC(int N) {
    int i = blockIdx.x * 256 + threadIdx.x;
    if (i < N) g_OFF[i] += g_BSUM[i >> 10];
}

__global__ void fillK(EIdx P) {
    int b = blockIdx.x, t = 0;
    while (t + 1 < 4 && b >= P.bofs[t + 1]) t++;
    int e = (b - P.bofs[t]) * 256 + threadIdx.x;
    if (e >= P.E[t]) return;
    int ci = P.cbase[t] + P.dst[t][e];
    int pos = atomicAdd(&g_CUR[ci], 1);
    g_ELIST[g_OFF[ci] + pos] = make_int2(e, P.src[t][e]);
}

__device__ __forceinline__ void stage_B(const __nv_bfloat16* gBh, const __nv_bfloat16* gBl,
                                        __nv_bfloat16* Bh, __nv_bfloat16* Bl, int tid)
{
    const uint4* bh = (const uint4*)gBh;
    const uint4* bl = (const uint4*)gBl;
#pragma unroll
    for (int i = 0; i < 8; i++) {
        int idx = tid + 256 * i;
        int row = idx >> 4, c = idx & 15;
        *(uint4*)(Bh + row * LDM + c * 8) = bh[idx];
        *(uint4*)(Bl + row * LDM + c * 8) = bl[idx];
    }
}

typedef wmma::fragment<wmma::accumulator, 16, 16, 16, float> AccFrag;

__device__ __forceinline__ void mma_pass(const __nv_bfloat16* A, const __nv_bfloat16* B1,
                                         const __nv_bfloat16* B2, AccFrag acc[2][4], int wid)
{
    int wr = (wid >> 1) * 32;
    int wc = (wid & 1) * 64;
#pragma unroll
    for (int kk = 0; kk < 8; kk++) {
        wmma::fragment<wmma::matrix_a, 16, 16, 16, __nv_bfloat16, wmma::row_major> ah[2];
#pragma unroll
        for (int i = 0; i < 2; i++)
            wmma::load_matrix_sync(ah[i], A + (wr + i * 16) * LDM + kk * 16, LDM);
#pragma unroll
        for (int j = 0; j < 4; j++) {
            wmma::fragment<wmma::matrix_b, 16, 16, 16, __nv_bfloat16, wmma::row_major> b1;
            wmma::load_matrix_sync(b1, B1 + (kk * 16) * LDM + wc + j * 16, LDM);
#pragma unroll
            for (int i = 0; i < 2; i++) wmma::mma_sync(acc[i][j], ah[i], b1, acc[i][j]);
            if (B2) {
                wmma::fragment<wmma::matrix_b, 16, 16, 16, __nv_bfloat16, wmma::row_major> b2;
                wmma::load_matrix_sync(b2, B2 + (kk * 16) * LDM + wc + j * 16, LDM);
#pragma unroll
                for (int i = 0; i < 2; i++) wmma::mma_sync(acc[i][j], ah[i], b2, acc[i][j]);
            }
        }
    }
}

__device__ __forceinline__ void store_acc(AccFrag acc[2][4], float* Cs, int wid) {
    int wr = (wid >> 1) * 32;
    int wc = (wid & 1) * 64;
#pragma unroll
    for (int i = 0; i < 2; i++)
#pragma unroll
        for (int j = 0; j < 4; j++)
            wmma::store_matrix_sync(Cs + (wr + i * 16) * 128 + wc + j * 16,
                                    acc[i][j], 128, wmma::mem_row_major);
}

// ---------------- batched wmma GEMM with gate-mode segments ----------------
// gmode 0: A = X (+X2), epilogue = +bias (fp32 or half out)
// gmode 1: A = gelu(cp@W1+gb1), epilogue = sigmoid(z + bias) -> half out
struct Seg { const float* X; const float* X2; const float* gb1;
             const __nv_bfloat16* Bh; const __nv_bfloat16* Bl;
             const float* bias; void* Y; int nrows; int tofs; int hout; int gmode; };
struct Segs { Seg s[5]; int nseg; };

__device__ __forceinline__ void fill_A_seg(const Seg& sg, int r0, int tid,
                                           __nv_bfloat16* A, int lo)
{
#pragma unroll 4
    for (int i = 0; i < 16; i++) {
        int idx = tid + 256 * i;
        int row = idx >> 5, c4 = idx & 31, gr = r0 + row;
        float4 v = make_float4(0.f, 0.f, 0.f, 0.f);
        if (gr < sg.nrows) {
            v = ((const float4*)sg.X)[(size_t)gr * 32 + c4];
            if (sg.X2) {
                float4 c = ((const float4*)sg.X2)[(size_t)gr * 32 + c4];
                v.x += c.x; v.y += c.y; v.z += c.z; v.w += c.w;
            }
        }
        *(uint2*)(A + row * LDM + c4 * 4) = pack_part(v, lo);
    }
}

__device__ __forceinline__ void fill_A_gate(const Seg& sg, int r0, int tid,
                                            __nv_bfloat16* A, int lo)
{
    const float* cp = sg.X;
    const float* W1 = sg.X2;
    const float* b1 = sg.gb1;
#pragma unroll 4
    for (int i = 0; i < 16; i++) {
        int idx = tid + 256 * i;
        int row = idx >> 5, c4 = idx & 31, ge = r0 + row;
        float4 h4 = make_float4(0.f, 0.f, 0.f, 0.f);
        if (ge < sg.nrows) {
            float x0 = cp[ge * 3 + 0], x1 = cp[ge * 3 + 1], x2 = cp[ge * 3 + 2];
            float4 w0 = ((const float4*)W1)[c4];
            float4 w1 = ((const float4*)(W1 + 128))[c4];
            float4 w2 = ((const float4*)(W1 + 256))[c4];
            float4 bb = ((const float4*)b1)[c4];
            h4.x = fmaf(x0, w0.x, fmaf(x1, w1.x, fmaf(x2, w2.x, bb.x)));
            h4.y = fmaf(x0, w0.y, fmaf(x1, w1.y, fmaf(x2, w2.y, bb.y)));
            h4.z = fmaf(x0, w0.z, fmaf(x1, w1.z, fmaf(x2, w2.z, bb.z)));
            h4.w = fmaf(x0, w0.w, fmaf(x1, w1.w, fmaf(x2, w2.w, bb.w)));
            h4.x = 0.5f * h4.x * (1.f + erff(h4.x * 0.70710678118654752f));
            h4.y = 0.5f * h4.y * (1.f + erff(h4.y * 0.70710678118654752f));
            h4.z = 0.5f * h4.z * (1.f + erff(h4.z * 0.70710678118654752f));
            h4.w = 0.5f * h4.w * (1.f + erff(h4.w * 0.70710678118654752f));
        }
        *(uint2*)(A + row * LDM + c4 * 4) = pack_part(h4, lo);
    }
}

__global__ void __launch_bounds__(256, 2) mm_gemm(Segs P) {
    extern __shared__ char sm[];
    __nv_bfloat16* A  = (__nv_bfloat16*)sm;
    __nv_bfloat16* Bh = A + 128 * LDM;
    __nv_bfloat16* Bl = Bh + 128 * LDM;
    float* Cs = (float*)sm;
    int b = blockIdx.x, si = 0;
    while (si + 1 < P.nseg && b >= P.s[si + 1].tofs) si++;
    Seg sg = P.s[si];
    int r0 = (b - sg.tofs) * 128;
    int tid = threadIdx.x, wid = tid >> 5;
    stage_B(sg.Bh, sg.Bl, Bh, Bl, tid);
    if (sg.gmode) fill_A_gate(sg, r0, tid, A, 0);
    else          fill_A_seg(sg, r0, tid, A, 0);
    __syncthreads();
    AccFrag acc[2][4];
#pragma unroll
    for (int i = 0; i < 2; i++)
#pragma unroll
        for (int j = 0; j < 4; j++) wmma::fill_fragment(acc[i][j], 0.f);
    mma_pass(A, Bh, Bl, acc, wid);
    __syncthreads();
    if (sg.gmode) fill_A_gate(sg, r0, tid, A, 1);
    else          fill_A_seg(sg, r0, tid, A, 1);
    __syncthreads();
    mma_pass(A, Bh, nullptr, acc, wid);
    __syncthreads();
    store_acc(acc, Cs, wid);
    __syncthreads();
#pragma unroll 4
    for (int i = 0; i < 16; i++) {
        int idx = tid + 256 * i;
        int row = idx >> 5, c4 = idx & 31, gr = r0 + row;
        if (gr < sg.nrows) {
            float4 v = ((float4*)Cs)[idx];
            float4 bb = ((const float4*)sg.bias)[c4];
            v.x += bb.x; v.y += bb.y; v.z += bb.z; v.w += bb.w;
            if (sg.gmode) {
                v.x = 1.f / (1.f + expf(-v.x));
                v.y = 1.f / (1.f + expf(-v.y));
                v.z = 1.f / (1.f + expf(-v.z));
                v.w = 1.f / (1.f + expf(-v.w));
            }
            if (sg.hout)
                st_half4((__half*)sg.Y + (size_t)gr * 128 + c4 * 4, v);
            else
                ((float4*)sg.Y)[(size_t)gr * 32 + c4] = v;
        }
    }
}

// ---------------- fused AD ----------------
struct AdP { const float* x[4]; int n[4]; int bofs[4]; };
__global__ void adK_f(AdP P) {
    int b = blockIdx.x, t = 0;
    while (t + 1 < 4 && b >= P.bofs[t + 1]) t++;
    int r = (b - P.bofs[t]) * 8 + (threadIdx.x >> 5);
    if (r >= P.n[t]) return;
    int lane = threadIdx.x & 31;
    float4 xv = ((const float4*)(P.x[t] + (size_t)r * 128))[lane];
    const float4* W4 = (const float4*)(g_WA + t * 512);
    float4 a0 = W4[4 * lane], a1 = W4[4 * lane + 1], a2 = W4[4 * lane + 2], a3 = W4[4 * lane + 3];
    float p0 = xv.x * a0.x + xv.y * a1.x + xv.z * a2.x + xv.w * a3.x;
    float p1 = xv.x * a0.y + xv.y * a1.y + xv.z * a2.y + xv.w * a3.y;
    float p2 = xv.x * a0.z + xv.y * a1.z + xv.z * a2.z + xv.w * a3.z;
    float p3 = xv.x * a0.w + xv.y * a1.w + xv.z * a2.w + xv.w * a3.w;
#pragma unroll
    for (int m = 16; m; m >>= 1) {
        p0 += __shfl_xor_sync(0xffffffffu, p0, m);
        p1 += __shfl_xor_sync(0xffffffffu, p1, m);
        p2 += __shfl_xor_sync(0xffffffffu, p2, m);
        p3 += __shfl_xor_sync(0xffffffffu, p3, m);
    }
    if (lane == 0)
        ((float4*)(g_AD + t * 200000))[r] =
            make_float4(p0 + g_BA[t * 4], p1 + g_BA[t * 4 + 1],
                        p2 + g_BA[t * 4 + 2], p3 + g_BA[t * 4 + 3]);
}

// ---------------- AS from half HS ----------------
__global__ void asK(const __half* __restrict__ HS, const float* __restrict__ at,
                    float* __restrict__ AS, int n)
{
    int r = (int)((blockIdx.x * (size_t)blockDim.x + threadIdx.x) >> 5);
    if (r >= n) return;
    int lane = threadIdx.x & 31;
    float4 h = ld_half4(HS + (size_t)r * 128 + lane * 4);
    float4 a = ((const float4*)at)[lane];
    float p = h.x * a.x + h.y * a.y + h.z * a.z + h.w * a.w;
    p += __shfl_xor_sync(0xffffffffu, p, 4);
    p += __shfl_xor_sync(0xffffffffu, p, 2);
    p += __shfl_xor_sync(0xffffffffu, p, 1);
    if ((lane & 7) == 0) AS[r * 4 + (lane >> 3)] = p;
}

// ---------------- gather aggregation, software-pipelined ----------------
struct AggP {
    const __half* HS[4];
    const float* AS[4];
    const float* AD[4];
    float* acc[4];
    const int* cg;
    const __half* G2;
    const float* attn2;
    int Nd[4]; int bofs[4]; int cbase[4]; int kind[4];
};

__global__ void __launch_bounds__(256) aggK(AggP P) {
    int b = blockIdx.x, t = 0;
    while (t + 1 < 4 && b >= P.bofs[t + 1]) t++;
    int d = (b - P.bofs[t]) * 8 + (threadIdx.x >> 5);
    if (d >= P.Nd[t]) return;
    int lane = threadIdx.x & 31, h = lane >> 3;
    int ci = P.cbase[t] + d;
    int start = g_OFF[ci], len = g_CNT[ci];
    int kind = P.kind[t];
    float adh = P.AD[t][(size_t)d * 4 + h];
    const __half* HS = P.HS[t];
    float4 accv = make_float4(0.f, 0.f, 0.f, 0.f);
    float ehs = 0.f;
    if (len == 0) {
        ((float4*)(P.acc[t] + (size_t)d * 128))[lane] = accv;
        return;
    }
    // prefetch slot 0
    int2 es = g_ELIST[start];
    float4 hs = ld_half4(HS + (size_t)es.y * 128 + lane * 4);
    int2 cgv = make_int2(0, 0);
    float4 gx = make_float4(0.f, 0.f, 0.f, 0.f);
    if (kind == 0) cgv = *(const int2*)(P.cg + 2 * es.x);
    else if (kind == 2) gx = ld_half4(P.G2 + (size_t)es.x * 128 + lane * 4);
    for (int i = 0; i < len; i++) {
        int2 es_c = es;
        float4 hs_c = hs;
        int2 cg_c = cgv;
        float4 g_c = gx;
        if (i + 1 < len) {   // issue next loads before processing current
            es = g_ELIST[start + i + 1];
            hs = ld_half4(HS + (size_t)es.y * 128 + lane * 4);
            if (kind == 0) cgv = *(const int2*)(P.cg + 2 * es.x);
            else if (kind == 2) gx = ld_half4(P.G2 + (size_t)es.x * 128 + lane * 4);
        }
        float4 msg;
        float eh;
        if (kind == 1) {
            msg = hs_c;
            float l = P.AS[t][es_c.y * 4 + h] + adh;
            eh = expf(l > 0.f ? l : 0.2f * l);
        } else {
            float p;
            if (kind == 0) {
                int comb = cg_c.x * 8 + cg_c.y;
                float4 g = ((const float4*)(g_GTAB + comb * 128))[lane];
                float4 ga = ((const float4*)(g_GTA0 + comb * 128))[lane];
                msg = make_float4(hs_c.x * g.x, hs_c.y * g.y, hs_c.z * g.z, hs_c.w * g.w);
                p = hs_c.x * ga.x + hs_c.y * ga.y + hs_c.z * ga.z + hs_c.w * ga.w;
            } else {
                float4 at = ((const float4*)P.attn2)[lane];
                msg = make_float4(hs_c.x * g_c.x, hs_c.y * g_c.y, hs_c.z * g_c.z, hs_c.w * g_c.w);
                p = msg.x * at.x + msg.y * at.y + msg.z * at.z + msg.w * at.w;
            }
            p += __shfl_xor_sync(0xffffffffu, p, 4);
            p += __shfl_xor_sync(0xffffffffu, p, 2);
            p += __shfl_xor_sync(0xffffffffu, p, 1);
            float l = p + adh;
            eh = expf(l > 0.f ? l : 0.2f * l);
        }
        accv.x = fmaf(eh, msg.x, accv.x);
        accv.y = fmaf(eh, msg.y, accv.y);
        accv.z = fmaf(eh, msg.z, accv.z);
        accv.w = fmaf(eh, msg.w, accv.w);
        ehs += eh;
    }
    float inv = (ehs > 0.f) ? 1.f / ehs : 0.f;
    ((float4*)(P.acc[t] + (size_t)d * 128))[lane] =
        make_float4(accv.x * inv, accv.y * inv, accv.z * inv, accv.w * inv);
}

__global__ void biasfill(float* __restrict__ out, const float* __restrict__ b, int n)
{
    int i = blockIdx.x * blockDim.x + threadIdx.x;
    if (i < n * 128) out[i] = b[i & 127];
}

// ---------------- launch (single stream) ----------------
extern "C" void kernel_launch(void* const* d_in, const int* in_sizes, int n_in,
                              void* d_out, int out_size)
{
    int iWsrc, ibsrc, iWdst, ibdst, iattn, itemb, isemb, iWg, ibg, iW1c, ib1c,
        iW2c, ib2c, iWout, ibout, icp, icg;
    int isrc[4], idst[4];
    if (in_sizes[4] == 65536) {            // layout A
        iWsrc = 4; ibsrc = 5; iWdst = 6; ibdst = 7; iattn = 8; itemb = 9; isemb = 10;
        iWg = 11; ibg = 12; iW1c = 13; ib1c = 14; iW2c = 15; ib2c = 16;
        iWout = 17; ibout = 18; icp = 19;
        isrc[0] = 20; idst[0] = 21; isrc[1] = 22; idst[1] = 23;
        isrc[2] = 24; idst[2] = 25; isrc[3] = 26; idst[3] = 27; icg = 28;
    } else {                               // layout B
        isrc[0] = 4; idst[0] = 5; isrc[1] = 6; idst[1] = 7;
        isrc[2] = 8; idst[2] = 9; isrc[3] = 10; idst[3] = 11;
        icg = 12; icp = 13;
        iWsrc = 14; ibsrc = 15; iWdst = 16; ibdst = 17; iattn = 18;
        itemb = 19; isemb = 20; iWg = 21; ibg = 22; iW1c = 23; ib1c = 24;
        iW2c = 25; ib2c = 26; iWout = 27; ibout = 28;
    }

    const float* x[4]  = {(const float*)d_in[0], (const float*)d_in[1],
                          (const float*)d_in[2], (const float*)d_in[3]};
    const float* Wsrc  = (const float*)d_in[iWsrc];
    const float* bsrc  = (const float*)d_in[ibsrc];
    const float* Wdst  = (const float*)d_in[iWdst];
    const float* bdst  = (const float*)d_in[ibdst];
    const float* attn  = (const float*)d_in[iattn];
    const float* temb  = (const float*)d_in[itemb];
    const float* semb  = (const float*)d_in[isemb];
    const float* Wg    = (const float*)d_in[iWg];
    const float* bg    = (const float*)d_in[ibg];
    const float* W1c   = (const float*)d_in[iW1c];
    const float* b1c   = (const float*)d_in[ib1c];
    const float* W2c   = (const float*)d_in[iW2c];
    const float* b2c   = (const float*)d_in[ib2c];
    const float* Wout  = (const float*)d_in[iWout];
    const float* bout  = (const float*)d_in[ibout];
    const float* cp    = (const float*)d_in[icp];
    const int* srcp[4] = {(const int*)d_in[isrc[0]], (const int*)d_in[isrc[1]],
                          (const int*)d_in[isrc[2]], (const int*)d_in[isrc[3]]};
    const int* dstp[4] = {(const int*)d_in[idst[0]], (const int*)d_in[idst[1]],
                          (const int*)d_in[idst[2]], (const int*)d_in[idst[3]]};
    const int* cg      = (const int*)d_in[icg];
    float* out = (float*)d_out;

    int Nn[4] = {in_sizes[0] / 128, in_sizes[1] / 128, in_sizes[2] / 128, in_sizes[3] / 128};
    int Ee[4] = {in_sizes[isrc[0]], in_sizes[isrc[1]], in_sizes[isrc[2]], in_sizes[isrc[3]]};
    int sidx[4] = {0, 1, 0, 2};
    int didx[4] = {1, 0, 3, 1};

    float *ACC, *AS, *AD;
    __half *Hh, *G2h;
    __nv_bfloat16 *WTh, *WTl;
    int *CNT, *CUR;
    cudaGetSymbolAddress((void**)&Hh, g_Hh);
    cudaGetSymbolAddress((void**)&G2h, g_G2h);
    cudaGetSymbolAddress((void**)&ACC, g_ACC);
    cudaGetSymbolAddress((void**)&AS, g_AS);
    cudaGetSymbolAddress((void**)&AD, g_AD);
    cudaGetSymbolAddress((void**)&WTh, g_WTh);
    cudaGetSymbolAddress((void**)&WTl, g_WTl);
    cudaGetSymbolAddress((void**)&CNT, g_CNT);
    cudaGetSymbolAddress((void**)&CUR, g_CUR);

    cudaFuncSetAttribute(mm_gemm, cudaFuncAttributeMaxDynamicSharedMemorySize, DYN_SMEM);

    size_t hofs[4] = {0, 50000, 80000, 130000};
    __half* HSp[4] = {Hh, Hh + hofs[1] * 128, Hh + hofs[2] * 128, Hh + hofs[3] * 128};
    float* AD_t[4]  = {AD, AD + 200000, AD + 400000, AD + 600000};
    int Ndst[4] = {Nn[didx[0]], Nn[didx[1]], Nn[didx[2]], Nn[didx[3]]};
    int cbase[4];
    cbase[0] = 0;
    for (int t = 1; t < 4; t++) cbase[t] = cbase[t - 1] + Ndst[t - 1];
    int NTOT = cbase[3] + Ndst[3];
    float* accT[4];
    for (int t = 0; t < 4; t++) accT[t] = ACC + (size_t)cbase[t] * 128;

    // ---- CSR build ----
    cudaMemsetAsync(CNT, 0, NTOT * sizeof(int));
    cudaMemsetAsync(CUR, 0, NTOT * sizeof(int));
    EIdx EI;
    int ebo = 0;
    for (int t = 0; t < 4; t++) {
        EI.dst[t] = dstp[t];
        EI.src[t] = srcp[t];
        EI.E[t] = Ee[t];
        EI.cbase[t] = cbase[t];
        EI.bofs[t] = ebo;
        ebo += (Ee[t] + 255) / 256;
    }
    histK<<<ebo, 256>>>(EI);
    int nb = (NTOT + 1023) / 1024;
    scanA<<<nb, 256>>>(NTOT);
    scanB<<<1, 128>>>(nb);
    scanC<<<(NTOT + 255) / 256, 256>>>(NTOT);
    fillK<<<ebo, 256>>>(EI);

    // ---- weight prep + tables ----
    WList wl;
    wl.w[0] = Wsrc;             wl.w[1] = Wsrc + 16384;
    wl.w[2] = Wsrc + 2 * 16384; wl.w[3] = Wsrc + 3 * 16384;
    wl.w[4] = Wout;             wl.w[5] = Wout + 16384;
    wl.w[6] = Wout + 3 * 16384; wl.w[7] = W2c;
    prep_w<<<dim3(8, 64), 256>>>(wl);
    prep_wa<<<4, 128>>>(Wdst, bdst, attn);
    gtabk<<<80, 128>>>(temb, semb, Wg, bg, attn);

    // ---- merged GEMM launch: 4 source transforms + gate GEMM ----
    Segs T;
    T.nseg = 5;
    int tcum = 0;
    for (int t = 0; t < 4; t++) {
        int ns = Nn[sidx[t]];
        T.s[t].X = x[sidx[t]];
        T.s[t].X2 = nullptr; T.s[t].gb1 = nullptr;
        T.s[t].Bh = WTh + t * 16384;
        T.s[t].Bl = WTl + t * 16384;
        T.s[t].bias = bsrc + t * 128;
        T.s[t].Y = HSp[t];
        T.s[t].nrows = ns;
        T.s[t].tofs = tcum;
        T.s[t].hout = 1; T.s[t].gmode = 0;
        tcum += (ns + 127) / 128;
    }
    T.s[4].X = cp; T.s[4].X2 = W1c; T.s[4].gb1 = b1c;
    T.s[4].Bh = WTh + 7 * 16384; T.s[4].Bl = WTl + 7 * 16384;
    T.s[4].bias = b2c; T.s[4].Y = G2h;
    T.s[4].nrows = Ee[2]; T.s[4].tofs = tcum;
    T.s[4].hout = 1; T.s[4].gmode = 1;
    tcum += (Ee[2] + 127) / 128;
    mm_gemm<<<tcum, 256, DYN_SMEM>>>(T);

    // ---- attn precomputes ----
    asK<<<(Nn[1] * 32 + 255) / 256, 256>>>(HSp[1], attn + 1 * 128, AS, Nn[1]);
    asK<<<(Nn[2] * 32 + 255) / 256, 256>>>(HSp[3], attn + 3 * 128, AS + 200000, Nn[2]);
    AdP PA;
    int abo = 0;
    for (int t = 0; t < 4; t++) {
        PA.x[t] = x[didx[t]];
        PA.n[t] = Ndst[t];
        PA.bofs[t] = abo;
        abo += (Ndst[t] + 7) / 8;
    }
    adK_f<<<abo, 256>>>(PA);

    // ---- gather aggregation ----
    AggP PG;
    PG.cg = cg; PG.G2 = G2h; PG.attn2 = attn + 2 * 128;
    int kindE[4] = {0, 1, 2, 1};
    const float* AS_t[4] = {nullptr, AS, nullptr, AS + 200000};
    int gbo = 0;
    for (int t = 0; t < 4; t++) {
        PG.HS[t] = HSp[t];
        PG.AS[t] = AS_t[t]; PG.AD[t] = AD_t[t];
        PG.acc[t] = accT[t];
        PG.Nd[t] = Ndst[t]; PG.cbase[t] = cbase[t]; PG.kind[t] = kindE[t];
        PG.bofs[t] = gbo;
        gbo += (Ndst[t] + 7) / 8;
    }
    aggK<<<gbo, 256>>>(PG);

    // ---- output GEMMs ----
    float* o_chem = out;
    float* o_gene = o_chem + (size_t)Nn[0] * 128;
    float* o_dis  = o_gene + (size_t)Nn[1] * 128;
    float* o_path = o_dis + (size_t)Nn[2] * 128;
    Segs O;
    O.nseg = 3;
    int b0 = (Nn[0] + 127) / 128;
    int b1 = (Nn[1] + 127) / 128;
    int b2 = (Nn[3] + 127) / 128;
    O.s[0] = {accT[1], nullptr, nullptr,
              WTh + 4 * 16384, WTl + 4 * 16384, bout,       o_chem, Nn[0], 0,       0, 0};
    O.s[1] = {accT[0], accT[3], nullptr,
              WTh + 5 * 16384, WTl + 5 * 16384, bout + 128, o_gene, Nn[1], b0,      0, 0};
    O.s[2] = {accT[2], nullptr, nullptr,
              WTh + 6 * 16384, WTl + 6 * 16384, bout + 384, o_path, Nn[3], b0 + b1, 0, 0};
    mm_gemm<<<b0 + b1 + b2, 256, DYN_SMEM>>>(O);
    biasfill<<<(Nn[2] * 128 + 255) / 256, 256>>>(o_dis, bout + 256, Nn[2]);
}

// round 15
// speedup vs baseline: 1.0807x; 1.0807x over previous
#include <cuda_runtime.h>
#include <cuda_bf16.h>
#include <cuda_fp16.h>
#include <mma.h>
#include <math.h>
#include <stdint.h>

using namespace nvcuda;

// ---------------- static scratch ----------------
__device__ __half g_Hh[140000 * 128];   // HS tables (half): t0@0 t1@50k t2@80k t3@130k
__device__ __half g_G2h[250000 * 128];  // per-edge continuous gate (t2), half
__device__ float g_ACC[115000 * 128];   // per-type NORMALIZED acc
__device__ float g_GTAB[80 * 128];      // categorical gate table
__device__ float g_GTA0[80 * 128];      // gate table * attn0
__device__ float g_AS[2 * 50000 * 4];   // per-src attn dots (t1 @0, t3 @200000)
__device__ float g_AD[4 * 50000 * 4];   // per-dst attn dots, per edge type
__device__ float g_WA[4 * 128 * 4];     // Wdst collapsed with attn
__device__ float g_BA[4 * 4];
__device__ __nv_bfloat16 g_WTh[8 * 16384]; // weights [k][n] row-major, bf16 hi
__device__ __nv_bfloat16 g_WTl[8 * 16384]; // weights [k][n] row-major, bf16 lo
// CSR scratch
__device__ int g_CNT[115008];
__device__ int g_OFF[115008];
__device__ int g_CUR[115008];
__device__ int g_BSUM[128];
__device__ int2 g_ELIST[1500000];       // (edge, src)

__device__ __forceinline__ float4 ld_half4(const __half* p) {
    uint2 u = *(const uint2*)p;
    __half2 a = *(__half2*)&u.x, b = *(__half2*)&u.y;
    float2 fa = __half22float2(a), fb = __half22float2(b);
    return make_float4(fa.x, fa.y, fb.x, fb.y);
}
__device__ __forceinline__ void st_half4(__half* p, float4 v) {
    __half2 a = __floats2half2_rn(v.x, v.y);
    __half2 b = __floats2half2_rn(v.z, v.w);
    uint2 u;
    u.x = *(uint32_t*)&a; u.y = *(uint32_t*)&b;
    *(uint2*)p = u;
}

__device__ __forceinline__ uint2 pack_part(float4 v, int lo) {
    __nv_bfloat16 hx = __float2bfloat16(v.x), hy = __float2bfloat16(v.y);
    __nv_bfloat16 hz = __float2bfloat16(v.z), hw = __float2bfloat16(v.w);
    if (lo) {
        hx = __float2bfloat16(v.x - __bfloat162float(hx));
        hy = __float2bfloat16(v.y - __bfloat162float(hy));
        hz = __float2bfloat16(v.z - __bfloat162float(hz));
        hw = __float2bfloat16(v.w - __bfloat162float(hw));
    }
    uint2 u;
    u.x = ((uint32_t)__bfloat16_as_ushort(hy) << 16) | __bfloat16_as_ushort(hx);
    u.y = ((uint32_t)__bfloat16_as_ushort(hw) << 16) | __bfloat16_as_ushort(hz);
    return u;
}

#define LDM 136
#define DYN_SMEM (3 * 128 * LDM * 2)    // A, Bh, Bl = 104448 B -> 2 blocks/SM

// ---------------- merged prep: weights split + WA + gate table ----------------
struct PrepP {
    const float* w[8];                  // 8 weight matrices to split
    const float* Wdst; const float* bdst; const float* attn;
    const float* te; const float* se; const float* Wg; const float* bg;
};
__global__ void prepAll(PrepP P) {
    int b = blockIdx.x;
    if (b < 512) {                      // prep_w: 8 matrices x 64 blocks
        int m = b >> 6;
        int idx = (b & 63) * 256 + threadIdx.x;
        float v = P.w[m][idx];
        __nv_bfloat16 h = __float2bfloat16(v);
        g_WTh[m * 16384 + idx] = h;
        g_WTl[m * 16384 + idx] = __float2bfloat16(v - __bfloat162float(h));
        return;
    }
    if (b < 516) {                      // prep_wa: 4 blocks (uses 128 of 256 threads)
        int t = b - 512, k = threadIdx.x;
        if (k >= 128) return;
        const float* W = P.Wdst + t * 16384;
        const float* at = P.attn + t * 128;
        float4 o;
        float* po = &o.x;
#pragma unroll
        for (int h = 0; h < 4; h++) {
            float s = 0.f;
            for (int dh = 0; dh < 32; dh++)
                s = fmaf(W[k * 128 + h * 32 + dh], at[h * 32 + dh], s);
            po[h] = s;
        }
        ((float4*)(g_WA + t * 512))[k] = o;
        if (k < 4) {
            const float* bb = P.bdst + t * 128;
            float s = 0.f;
            for (int dh = 0; dh < 32; dh++) s = fmaf(bb[k * 32 + dh], at[k * 32 + dh], s);
            g_BA[t * 4 + k] = s;
        }
        return;
    }
    {                                   // gtabk: 40 blocks x 256 threads = 80 rows x 128
        int rb = (b - 516) * 2 + (threadIdx.x >> 7);   // row 0..79
        int c = threadIdx.x & 127;
        if (rb >= 80) return;
        int a = rb >> 3, bb = rb & 7;
        float s = P.bg[c];
#pragma unroll 8
        for (int j = 0; j < 32; j++) s = fmaf(P.te[a * 32 + j], P.Wg[j * 128 + c], s);
#pragma unroll 8
        for (int j = 0; j < 32; j++) s = fmaf(P.se[bb * 32 + j], P.Wg[(32 + j) * 128 + c], s);
        float g = 1.f / (1.f + expf(-s));
        g_GTAB[rb * 128 + c] = g;
        g_GTA0[rb * 128 + c] = g * P.attn[c];   // attn row 0
    }
}

// ---------------- CSR build ----------------
struct EIdx { const int* dst[4]; const int* src[4]; int E[4]; int bofs[4]; int cbase[4]; };

__global__ void histK(EIdx P) {
    int b = blockIdx.x, t = 0;
    while (t + 1 < 4 && b >= P.bofs[t + 1]) t++;
    int e = (b - P.bofs[t]) * 256 + threadIdx.x;
    if (e >= P.E[t]) return;
    atomicAdd(&g_CNT[P.cbase[t] + P.dst[t][e]], 1);
}

__global__ void scanA(int N) {
    int base = blockIdx.x * 1024;
    int tid = threadIdx.x, lane = tid & 31, wid = tid >> 5;
    int v[4];
#pragma unroll
    for (int k = 0; k < 4; k++) {
        int i = base + tid * 4 + k;
        v[k] = (i < N) ? g_CNT[i] : 0;
    }
    int tsum = v[0] + v[1] + v[2] + v[3];
    int x = tsum;
#pragma unroll
    for (int o = 1; o < 32; o <<= 1) {
        int y = __shfl_up_sync(0xffffffffu, x, o);
        if (lane >= o) x += y;
    }
    __shared__ int ws[8];
    if (lane == 31) ws[wid] = x;
    __syncthreads();
    if (tid == 0) {
        int a = 0;
        for (int w = 0; w < 8; w++) { int tt = ws[w]; ws[w] = a; a += tt; }
        g_BSUM[blockIdx.x] = a;
    }
    __syncthreads();
    int run = x - tsum + ws[wid];
#pragma unroll
    for (int k = 0; k < 4; k++) {
        int i = base + tid * 4 + k;
        if (i < N) g_OFF[i] = run;
        run += v[k];
    }
}

__global__ void scanB(int nb) {
    int tid = threadIdx.x, lane = tid & 31, wid = tid >> 5;
    int v = (tid < nb) ? g_BSUM[tid] : 0;
    int x = v;
#pragma unroll
    for (int o = 1; o < 32; o <<= 1) {
        int y = __shfl_up_sync(0xffffffffu, x, o);
        if (lane >= o) x += y;
    }
    __shared__ int ws[4];
    if (lane == 31) ws[wid] = x;
    __syncthreads();
    int add = 0;
    for (int w = 0; w < wid; w++) add += ws[w];
    if (tid < nb) g_BSUM[tid] = x - v + add;
}

__global__ void scanC(int N) {
    int i = blockIdx.x * 256 + threadIdx.x;
    if (i < N) g_OFF[i] += g_BSUM[i >> 10];
}

__global__ void fillK(EIdx P) {
    int b = blockIdx.x, t = 0;
    while (t + 1 < 4 && b >= P.bofs[t + 1]) t++;
    int e = (b - P.bofs[t]) * 256 + threadIdx.x;
    if (e >= P.E[t]) return;
    int ci = P.cbase[t] + P.dst[t][e];
    int pos = atomicAdd(&g_CUR[ci], 1);
    g_ELIST[g_OFF[ci] + pos] = make_int2(e, P.src[t][e]);
}

__device__ __forceinline__ void stage_B(const __nv_bfloat16* gBh, const __nv_bfloat16* gBl,
                                        __nv_bfloat16* Bh, __nv_bfloat16* Bl, int tid)
{
    const uint4* bh = (const uint4*)gBh;
    const uint4* bl = (const uint4*)gBl;
#pragma unroll
    for (int i = 0; i < 8; i++) {
        int idx = tid + 256 * i;
        int row = idx >> 4, c = idx & 15;
        *(uint4*)(Bh + row * LDM + c * 8) = bh[idx];
        *(uint4*)(Bl + row * LDM + c * 8) = bl[idx];
    }
}

typedef wmma::fragment<wmma::accumulator, 16, 16, 16, float> AccFrag;

__device__ __forceinline__ void mma_pass(const __nv_bfloat16* A, const __nv_bfloat16* B1,
                                         const __nv_bfloat16* B2, AccFrag acc[2][4], int wid)
{
    int wr = (wid >> 1) * 32;
    int wc = (wid & 1) * 64;
#pragma unroll
    for (int kk = 0; kk < 8; kk++) {
        wmma::fragment<wmma::matrix_a, 16, 16, 16, __nv_bfloat16, wmma::row_major> ah[2];
#pragma unroll
        for (int i = 0; i < 2; i++)
            wmma::load_matrix_sync(ah[i], A + (wr + i * 16) * LDM + kk * 16, LDM);
#pragma unroll
        for (int j = 0; j < 4; j++) {
            wmma::fragment<wmma::matrix_b, 16, 16, 16, __nv_bfloat16, wmma::row_major> b1;
            wmma::load_matrix_sync(b1, B1 + (kk * 16) * LDM + wc + j * 16, LDM);
#pragma unroll
            for (int i = 0; i < 2; i++) wmma::mma_sync(acc[i][j], ah[i], b1, acc[i][j]);
            if (B2) {
                wmma::fragment<wmma::matrix_b, 16, 16, 16, __nv_bfloat16, wmma::row_major> b2;
                wmma::load_matrix_sync(b2, B2 + (kk * 16) * LDM + wc + j * 16, LDM);
#pragma unroll
                for (int i = 0; i < 2; i++) wmma::mma_sync(acc[i][j], ah[i], b2, acc[i][j]);
            }
        }
    }
}

__device__ __forceinline__ void store_acc(AccFrag acc[2][4], float* Cs, int wid) {
    int wr = (wid >> 1) * 32;
    int wc = (wid & 1) * 64;
#pragma unroll
    for (int i = 0; i < 2; i++)
#pragma unroll
        for (int j = 0; j < 4; j++)
            wmma::store_matrix_sync(Cs + (wr + i * 16) * 128 + wc + j * 16,
                                    acc[i][j], 128, wmma::mem_row_major);
}

// ---------------- batched wmma GEMM with gate-mode segments ----------------
// gmode 0: A = X (+X2) hi/lo 3-pass, epilogue = +bias
// gmode 1: A = gelu(cp@W1+gb1) SINGLE-pass hi (B hi/lo kept), epilogue = sigmoid -> half
struct Seg { const float* X; const float* X2; const float* gb1;
             const __nv_bfloat16* Bh; const __nv_bfloat16* Bl;
             const float* bias; void* Y; int nrows; int tofs; int hout; int gmode; };
struct Segs { Seg s[5]; int nseg; };

__device__ __forceinline__ void fill_A_seg(const Seg& sg, int r0, int tid,
                                           __nv_bfloat16* A, int lo)
{
#pragma unroll 4
    for (int i = 0; i < 16; i++) {
        int idx = tid + 256 * i;
        int row = idx >> 5, c4 = idx & 31, gr = r0 + row;
        float4 v = make_float4(0.f, 0.f, 0.f, 0.f);
        if (gr < sg.nrows) {
            v = ((const float4*)sg.X)[(size_t)gr * 32 + c4];
            if (sg.X2) {
                float4 c = ((const float4*)sg.X2)[(size_t)gr * 32 + c4];
                v.x += c.x; v.y += c.y; v.z += c.z; v.w += c.w;
            }
        }
        *(uint2*)(A + row * LDM + c4 * 4) = pack_part(v, lo);
    }
}

__device__ __forceinline__ void fill_A_gate(const Seg& sg, int r0, int tid,
                                            __nv_bfloat16* A)
{
    const float* cp = sg.X;
    const float* W1 = sg.X2;
    const float* b1 = sg.gb1;
#pragma unroll 4
    for (int i = 0; i < 16; i++) {
        int idx = tid + 256 * i;
        int row = idx >> 5, c4 = idx & 31, ge = r0 + row;
        float4 h4 = make_float4(0.f, 0.f, 0.f, 0.f);
        if (ge < sg.nrows) {
            float x0 = cp[ge * 3 + 0], x1 = cp[ge * 3 + 1], x2 = cp[ge * 3 + 2];
            float4 w0 = ((const float4*)W1)[c4];
            float4 w1 = ((const float4*)(W1 + 128))[c4];
            float4 w2 = ((const float4*)(W1 + 256))[c4];
            float4 bb = ((const float4*)b1)[c4];
            h4.x = fmaf(x0, w0.x, fmaf(x1, w1.x, fmaf(x2, w2.x, bb.x)));
            h4.y = fmaf(x0, w0.y, fmaf(x1, w1.y, fmaf(x2, w2.y, bb.y)));
            h4.z = fmaf(x0, w0.z, fmaf(x1, w1.z, fmaf(x2, w2.z, bb.z)));
            h4.w = fmaf(x0, w0.w, fmaf(x1, w1.w, fmaf(x2, w2.w, bb.w)));
            h4.x = 0.5f * h4.x * (1.f + erff(h4.x * 0.70710678118654752f));
            h4.y = 0.5f * h4.y * (1.f + erff(h4.y * 0.70710678118654752f));
            h4.z = 0.5f * h4.z * (1.f + erff(h4.z * 0.70710678118654752f));
            h4.w = 0.5f * h4.w * (1.f + erff(h4.w * 0.70710678118654752f));
        }
        *(uint2*)(A + row * LDM + c4 * 4) = pack_part(h4, 0);
    }
}

__global__ void __launch_bounds__(256, 2) mm_gemm(Segs P) {
    extern __shared__ char sm[];
    __nv_bfloat16* A  = (__nv_bfloat16*)sm;
    __nv_bfloat16* Bh = A + 128 * LDM;
    __nv_bfloat16* Bl = Bh + 128 * LDM;
    float* Cs = (float*)sm;
    int b = blockIdx.x, si = 0;
    while (si + 1 < P.nseg && b >= P.s[si + 1].tofs) si++;
    Seg sg = P.s[si];
    int r0 = (b - sg.tofs) * 128;
    int tid = threadIdx.x, wid = tid >> 5;
    stage_B(sg.Bh, sg.Bl, Bh, Bl, tid);
    if (sg.gmode) fill_A_gate(sg, r0, tid, A);
    else          fill_A_seg(sg, r0, tid, A, 0);
    __syncthreads();
    AccFrag acc[2][4];
#pragma unroll
    for (int i = 0; i < 2; i++)
#pragma unroll
        for (int j = 0; j < 4; j++) wmma::fill_fragment(acc[i][j], 0.f);
    mma_pass(A, Bh, Bl, acc, wid);
    if (!sg.gmode) {                     // lo-correction pass only for non-gate
        __syncthreads();
        fill_A_seg(sg, r0, tid, A, 1);
        __syncthreads();
        mma_pass(A, Bh, nullptr, acc, wid);
    }
    __syncthreads();
    store_acc(acc, Cs, wid);
    __syncthreads();
#pragma unroll 4
    for (int i = 0; i < 16; i++) {
        int idx = tid + 256 * i;
        int row = idx >> 5, c4 = idx & 31, gr = r0 + row;
        if (gr < sg.nrows) {
            float4 v = ((float4*)Cs)[idx];
            float4 bb = ((const float4*)sg.bias)[c4];
            v.x += bb.x; v.y += bb.y; v.z += bb.z; v.w += bb.w;
            if (sg.gmode) {
                v.x = 1.f / (1.f + expf(-v.x));
                v.y = 1.f / (1.f + expf(-v.y));
                v.z = 1.f / (1.f + expf(-v.z));
                v.w = 1.f / (1.f + expf(-v.w));
            }
            if (sg.hout)
                st_half4((__half*)sg.Y + (size_t)gr * 128 + c4 * 4, v);
            else
                ((float4*)sg.Y)[(size_t)gr * 32 + c4] = v;
        }
    }
}

// ---------------- fused pre-edge kernel: asK(t1), asK(t3), adK(all) ----------------
struct PreP {
    const __half* HS1; const __half* HS3;     // HS tables for t1, t3
    const float* attn1; const float* attn3;
    const float* x[4];                        // dst-node features per edge type
    int nAS1, nAS3;
    int n[4];
    int bofs[6];                              // 0:AS1 1:AS3 2..5:AD t0..t3
};
__global__ void preEdge(PreP P) {
    int b = blockIdx.x, seg = 0;
    while (seg + 1 < 6 && b >= P.bofs[seg + 1]) seg++;
    int r = (b - P.bofs[seg]) * 8 + (threadIdx.x >> 5);
    int lane = threadIdx.x & 31;
    if (seg < 2) {                            // AS for t1 / t3
        int n = seg == 0 ? P.nAS1 : P.nAS3;
        if (r >= n) return;
        const __half* HS = seg == 0 ? P.HS1 : P.HS3;
        const float* at = seg == 0 ? P.attn1 : P.attn3;
        float* AS = g_AS + seg * 200000;
        float4 h = ld_half4(HS + (size_t)r * 128 + lane * 4);
        float4 a = ((const float4*)at)[lane];
        float p = h.x * a.x + h.y * a.y + h.z * a.z + h.w * a.w;
        p += __shfl_xor_sync(0xffffffffu, p, 4);
        p += __shfl_xor_sync(0xffffffffu, p, 2);
        p += __shfl_xor_sync(0xffffffffu, p, 1);
        if ((lane & 7) == 0) AS[r * 4 + (lane >> 3)] = p;
        return;
    }
    int t = seg - 2;
    if (r >= P.n[t]) return;
    float4 xv = ((const float4*)(P.x[t] + (size_t)r * 128))[lane];
    const float4* W4 = (const float4*)(g_WA + t * 512);
    float4 a0 = W4[4 * lane], a1 = W4[4 * lane + 1], a2 = W4[4 * lane + 2], a3 = W4[4 * lane + 3];
    float p0 = xv.x * a0.x + xv.y * a1.x + xv.z * a2.x + xv.w * a3.x;
    float p1 = xv.x * a0.y + xv.y * a1.y + xv.z * a2.y + xv.w * a3.y;
    float p2 = xv.x * a0.z + xv.y * a1.z + xv.z * a2.z + xv.w * a3.z;
    float p3 = xv.x * a0.w + xv.y * a1.w + xv.z * a2.w + xv.w * a3.w;
#pragma unroll
    for (int m = 16; m; m >>= 1) {
        p0 += __shfl_xor_sync(0xffffffffu, p0, m);
        p1 += __shfl_xor_sync(0xffffffffu, p1, m);
        p2 += __shfl_xor_sync(0xffffffffu, p2, m);
        p3 += __shfl_xor_sync(0xffffffffu, p3, m);
    }
    if (lane == 0)
        ((float4*)(g_AD + t * 200000))[r] =
            make_float4(p0 + g_BA[t * 4], p1 + g_BA[t * 4 + 1],
                        p2 + g_BA[t * 4 + 2], p3 + g_BA[t * 4 + 3]);
}

// ---------------- gather aggregation ----------------
struct AggP {
    const __half* HS[4];
    const float* AS[4];
    const float* AD[4];
    float* acc[4];
    const int* cg;
    const __half* G2;
    const float* attn2;
    int Nd[4]; int bofs[4]; int cbase[4]; int kind[4];
};

__global__ void __launch_bounds__(256) aggK(AggP P) {
    int b = blockIdx.x, t = 0;
    while (t + 1 < 4 && b >= P.bofs[t + 1]) t++;
    int d = (b - P.bofs[t]) * 8 + (threadIdx.x >> 5);
    if (d >= P.Nd[t]) return;
    int lane = threadIdx.x & 31, h = lane >> 3;
    int ci = P.cbase[t] + d;
    int start = g_OFF[ci], len = g_CNT[ci];
    int kind = P.kind[t];
    float adh = P.AD[t][(size_t)d * 4 + h];
    const __half* HS = P.HS[t];
    float4 accv = make_float4(0.f, 0.f, 0.f, 0.f);
    float ehs = 0.f;
    if (len == 0) {
        ((float4*)(P.acc[t] + (size_t)d * 128))[lane] = accv;
        return;
    }
    int2 es = g_ELIST[start];
    float4 hs = ld_half4(HS + (size_t)es.y * 128 + lane * 4);
    int2 cgv = make_int2(0, 0);
    float4 gx = make_float4(0.f, 0.f, 0.f, 0.f);
    if (kind == 0) cgv = *(const int2*)(P.cg + 2 * es.x);
    else if (kind == 2) gx = ld_half4(P.G2 + (size_t)es.x * 128 + lane * 4);
    for (int i = 0; i < len; i++) {
        int2 es_c = es;
        float4 hs_c = hs;
        int2 cg_c = cgv;
        float4 g_c = gx;
        if (i + 1 < len) {
            es = g_ELIST[start + i + 1];
            hs = ld_half4(HS + (size_t)es.y * 128 + lane * 4);
            if (kind == 0) cgv = *(const int2*)(P.cg + 2 * es.x);
            else if (kind == 2) gx = ld_half4(P.G2 + (size_t)es.x * 128 + lane * 4);
        }
        float4 msg;
        float eh;
        if (kind == 1) {
            msg = hs_c;
            float l = P.AS[t][es_c.y * 4 + h] + adh;
            eh = expf(l > 0.f ? l : 0.2f * l);
        } else {
            float p;
            if (kind == 0) {
                int comb = cg_c.x * 8 + cg_c.y;
                float4 g = ((const float4*)(g_GTAB + comb * 128))[lane];
                float4 ga = ((const float4*)(g_GTA0 + comb * 128))[lane];
                msg = make_float4(hs_c.x * g.x, hs_c.y * g.y, hs_c.z * g.z, hs_c.w * g.w);
                p = hs_c.x * ga.x + hs_c.y * ga.y + hs_c.z * ga.z + hs_c.w * ga.w;
            } else {
                float4 at = ((const float4*)P.attn2)[lane];
                msg = make_float4(hs_c.x * g_c.x, hs_c.y * g_c.y, hs_c.z * g_c.z, hs_c.w * g_c.w);
                p = msg.x * at.x + msg.y * at.y + msg.z * at.z + msg.w * at.w;
            }
            p += __shfl_xor_sync(0xffffffffu, p, 4);
            p += __shfl_xor_sync(0xffffffffu, p, 2);
            p += __shfl_xor_sync(0xffffffffu, p, 1);
            float l = p + adh;
            eh = expf(l > 0.f ? l : 0.2f * l);
        }
        accv.x = fmaf(eh, msg.x, accv.x);
        accv.y = fmaf(eh, msg.y, accv.y);
        accv.z = fmaf(eh, msg.z, accv.z);
        accv.w = fmaf(eh, msg.w, accv.w);
        ehs += eh;
    }
    float inv = (ehs > 0.f) ? 1.f / ehs : 0.f;
    ((float4*)(P.acc[t] + (size_t)d * 128))[lane] =
        make_float4(accv.x * inv, accv.y * inv, accv.z * inv, accv.w * inv);
}

__global__ void biasfill(float* __restrict__ out, const float* __restrict__ b, int n)
{
    int i = blockIdx.x * blockDim.x + threadIdx.x;
    if (i < n * 128) out[i] = b[i & 127];
}

// ---------------- launch (single stream) ----------------
extern "C" void kernel_launch(void* const* d_in, const int* in_sizes, int n_in,
                              void* d_out, int out_size)
{
    int iWsrc, ibsrc, iWdst, ibdst, iattn, itemb, isemb, iWg, ibg, iW1c, ib1c,
        iW2c, ib2c, iWout, ibout, icp, icg;
    int isrc[4], idst[4];
    if (in_sizes[4] == 65536) {            // layout A
        iWsrc = 4; ibsrc = 5; iWdst = 6; ibdst = 7; iattn = 8; itemb = 9; isemb = 10;
        iWg = 11; ibg = 12; iW1c = 13; ib1c = 14; iW2c = 15; ib2c = 16;
        iWout = 17; ibout = 18; icp = 19;
        isrc[0] = 20; idst[0] = 21; isrc[1] = 22; idst[1] = 23;
        isrc[2] = 24; idst[2] = 25; isrc[3] = 26; idst[3] = 27; icg = 28;
    } else {                               // layout B
        isrc[0] = 4; idst[0] = 5; isrc[1] = 6; idst[1] = 7;
        isrc[2] = 8; idst[2] = 9; isrc[3] = 10; idst[3] = 11;
        icg = 12; icp = 13;
        iWsrc = 14; ibsrc = 15; iWdst = 16; ibdst = 17; iattn = 18;
        itemb = 19; isemb = 20; iWg = 21; ibg = 22; iW1c = 23; ib1c = 24;
        iW2c = 25; ib2c = 26; iWout = 27; ibout = 28;
    }

    const float* x[4]  = {(const float*)d_in[0], (const float*)d_in[1],
                          (const float*)d_in[2], (const float*)d_in[3]};
    const float* Wsrc  = (const float*)d_in[iWsrc];
    const float* bsrc  = (const float*)d_in[ibsrc];
    const float* Wdst  = (const float*)d_in[iWdst];
    const float* bdst  = (const float*)d_in[ibdst];
    const float* attn  = (const float*)d_in[iattn];
    const float* temb  = (const float*)d_in[itemb];
    const float* semb  = (const float*)d_in[isemb];
    const float* Wg    = (const float*)d_in[iWg];
    const float* bg    = (const float*)d_in[ibg];
    const float* W1c   = (const float*)d_in[iW1c];
    const float* b1c   = (const float*)d_in[ib1c];
    const float* W2c   = (const float*)d_in[iW2c];
    const float* b2c   = (const float*)d_in[ib2c];
    const float* Wout  = (const float*)d_in[iWout];
    const float* bout  = (const float*)d_in[ibout];
    const float* cp    = (const float*)d_in[icp];
    const int* srcp[4] = {(const int*)d_in[isrc[0]], (const int*)d_in[isrc[1]],
                          (const int*)d_in[isrc[2]], (const int*)d_in[isrc[3]]};
    const int* dstp[4] = {(const int*)d_in[idst[0]], (const int*)d_in[idst[1]],
                          (const int*)d_in[idst[2]], (const int*)d_in[idst[3]]};
    const int* cg      = (const int*)d_in[icg];
    float* out = (float*)d_out;

    int Nn[4] = {in_sizes[0] / 128, in_sizes[1] / 128, in_sizes[2] / 128, in_sizes[3] / 128};
    int Ee[4] = {in_sizes[isrc[0]], in_sizes[isrc[1]], in_sizes[isrc[2]], in_sizes[isrc[3]]};
    int sidx[4] = {0, 1, 0, 2};
    int didx[4] = {1, 0, 3, 1};

    float *ACC, *AS, *AD;
    __half *Hh, *G2h;
    __nv_bfloat16 *WTh, *WTl;
    int *CNT, *CUR;
    cudaGetSymbolAddress((void**)&Hh, g_Hh);
    cudaGetSymbolAddress((void**)&G2h, g_G2h);
    cudaGetSymbolAddress((void**)&ACC, g_ACC);
    cudaGetSymbolAddress((void**)&AS, g_AS);
    cudaGetSymbolAddress((void**)&AD, g_AD);
    cudaGetSymbolAddress((void**)&WTh, g_WTh);
    cudaGetSymbolAddress((void**)&WTl, g_WTl);
    cudaGetSymbolAddress((void**)&CNT, g_CNT);
    cudaGetSymbolAddress((void**)&CUR, g_CUR);

    cudaFuncSetAttribute(mm_gemm, cudaFuncAttributeMaxDynamicSharedMemorySize, DYN_SMEM);

    size_t hofs[4] = {0, 50000, 80000, 130000};
    __half* HSp[4] = {Hh, Hh + hofs[1] * 128, Hh + hofs[2] * 128, Hh + hofs[3] * 128};
    float* AD_t[4]  = {AD, AD + 200000, AD + 400000, AD + 600000};
    int Ndst[4] = {Nn[didx[0]], Nn[didx[1]], Nn[didx[2]], Nn[didx[3]]};
    int cbase[4];
    cbase[0] = 0;
    for (int t = 1; t < 4; t++) cbase[t] = cbase[t - 1] + Ndst[t - 1];
    int NTOT = cbase[3] + Ndst[3];
    float* accT[4];
    for (int t = 0; t < 4; t++) accT[t] = ACC + (size_t)cbase[t] * 128;

    // ---- CSR build ----
    cudaMemsetAsync(CNT, 0, NTOT * sizeof(int));
    cudaMemsetAsync(CUR, 0, NTOT * sizeof(int));
    EIdx EI;
    int ebo = 0;
    for (int t = 0; t < 4; t++) {
        EI.dst[t] = dstp[t];
        EI.src[t] = srcp[t];
        EI.E[t] = Ee[t];
        EI.cbase[t] = cbase[t];
        EI.bofs[t] = ebo;
        ebo += (Ee[t] + 255) / 256;
    }
    histK<<<ebo, 256>>>(EI);
    int nb = (NTOT + 1023) / 1024;
    scanA<<<nb, 256>>>(NTOT);
    scanB<<<1, 128>>>(nb);
    scanC<<<(NTOT + 255) / 256, 256>>>(NTOT);
    fillK<<<ebo, 256>>>(EI);

    // ---- merged prep launch ----
    PrepP PR;
    PR.w[0] = Wsrc;             PR.w[1] = Wsrc + 16384;
    PR.w[2] = Wsrc + 2 * 16384; PR.w[3] = Wsrc + 3 * 16384;
    PR.w[4] = Wout;             PR.w[5] = Wout + 16384;
    PR.w[6] = Wout + 3 * 16384; PR.w[7] = W2c;
    PR.Wdst = Wdst; PR.bdst = bdst; PR.attn = attn;
    PR.te = temb; PR.se = semb; PR.Wg = Wg; PR.bg = bg;
    prepAll<<<556, 256>>>(PR);

    // ---- merged GEMM launch: transforms + gate ----
    Segs T;
    T.nseg = 5;
    int tcum = 0;
    for (int t = 0; t < 4; t++) {
        int ns = Nn[sidx[t]];
        T.s[t].X = x[sidx[t]];
        T.s[t].X2 = nullptr; T.s[t].gb1 = nullptr;
        T.s[t].Bh = WTh + t * 16384;
        T.s[t].Bl = WTl + t * 16384;
        T.s[t].bias = bsrc + t * 128;
        T.s[t].Y = HSp[t];
        T.s[t].nrows = ns;
        T.s[t].tofs = tcum;
        T.s[t].hout = 1; T.s[t].gmode = 0;
        tcum += (ns + 127) / 128;
    }
    T.s[4].X = cp; T.s[4].X2 = W1c; T.s[4].gb1 = b1c;
    T.s[4].Bh = WTh + 7 * 16384; T.s[4].Bl = WTl + 7 * 16384;
    T.s[4].bias = b2c; T.s[4].Y = G2h;
    T.s[4].nrows = Ee[2]; T.s[4].tofs = tcum;
    T.s[4].hout = 1; T.s[4].gmode = 1;
    tcum += (Ee[2] + 127) / 128;
    mm_gemm<<<tcum, 256, DYN_SMEM>>>(T);

    // ---- fused pre-edge (AS t1/t3 + AD all) ----
    PreP PP;
    PP.HS1 = HSp[1]; PP.HS3 = HSp[3];
    PP.attn1 = attn + 128; PP.attn3 = attn + 3 * 128;
    PP.nAS1 = Nn[1]; PP.nAS3 = Nn[2];
    int pbo = 0;
    PP.bofs[0] = pbo; pbo += (Nn[1] + 7) / 8;
    PP.bofs[1] = pbo; pbo += (Nn[2] + 7) / 8;
    for (int t = 0; t < 4; t++) {
        PP.x[t] = x[didx[t]];
        PP.n[t] = Ndst[t];
        PP.bofs[2 + t] = pbo;
        pbo += (Ndst[t] + 7) / 8;
    }
    preEdge<<<pbo, 256>>>(PP);

    // ---- gather aggregation ----
    AggP PG;
    PG.cg = cg; PG.G2 = G2h; PG.attn2 = attn + 2 * 128;
    int kindE[4] = {0, 1, 2, 1};
    const float* AS_t[4] = {nullptr, AS, nullptr, AS + 200000};
    int gbo = 0;
    for (int t = 0; t < 4; t++) {
        PG.HS[t] = HSp[t];
        PG.AS[t] = AS_t[t]; PG.AD[t] = AD_t[t];
        PG.acc[t] = accT[t];
        PG.Nd[t] = Ndst[t]; PG.cbase[t] = cbase[t]; PG.kind[t] = kindE[t];
        PG.bofs[t] = gbo;
        gbo += (Ndst[t] + 7) / 8;
    }
    aggK<<<gbo, 256>>>(PG);

    // ---- output GEMMs ----
    float* o_chem = out;
    float* o_gene = o_chem + (size_t)Nn[0] * 128;
    float* o_dis  = o_gene + (size_t)Nn[1] * 128;
    float* o_path = o_dis + (size_t)Nn[2] * 128;
    Segs O;
    O.nseg = 3;
    int b0 = (Nn[0] + 127) / 128;
    int b1 = (Nn[1] + 127) / 128;
    int b2 = (Nn[3] + 127) / 128;
    O.s[0] = {accT[1], nullptr, nullptr,
              WTh + 4 * 16384, WTl + 4 * 16384, bout,       o_chem, Nn[0], 0,       0, 0};
    O.s[1] = {accT[0], accT[3], nullptr,
              WTh + 5 * 16384, WTl + 5 * 16384, bout + 128, o_gene, Nn[1], b0,      0, 0};
    O.s[2] = {accT[2], nullptr, nullptr,
              WTh + 6 * 16384, WTl + 6 * 16384, bout + 384, o_path, Nn[3], b0 + b1, 0, 0};
    mm_gemm<<<b0 + b1 + b2, 256, DYN_SMEM>>>(O);
    biasfill<<<(Nn[2] * 128 + 255) / 256, 256>>>(o_dis, bout + 256, Nn[2]);
}

// round 16
// speedup vs baseline: 1.0926x; 1.0110x over previous
#include <cuda_runtime.h>
#include <cuda_bf16.h>
#include <cuda_fp16.h>
#include <mma.h>
#include <math.h>
#include <stdint.h>

using namespace nvcuda;

// ---------------- static scratch ----------------
__device__ __half g_Hh[140000 * 128];   // HS tables (half): t0@0 t1@50k t2@80k t3@130k
__device__ __half g_G2h[250000 * 128];  // per-edge continuous gate (t2), half
__device__ float g_ACC[115000 * 128];   // per-type NORMALIZED acc
__device__ float g_GTAB[80 * 128];      // categorical gate table
__device__ float g_GTA0[80 * 128];      // gate table * attn0
__device__ float g_AS[2 * 50000 * 4];   // per-src attn dots (t1 @0, t3 @200000)
__device__ float g_AD[4 * 50000 * 4];   // per-dst attn dots, per edge type
__device__ float g_WA[4 * 128 * 4];     // Wdst collapsed with attn
__device__ float g_BA[4 * 4];
__device__ __nv_bfloat16 g_WTh[8 * 16384]; // weights [k][n] row-major, bf16 hi
__device__ __nv_bfloat16 g_WTl[8 * 16384]; // weights [k][n] row-major, bf16 lo
// CSR scratch: [0,115008) counts, [115008, 230016) cursors
__device__ int g_CSR[2 * 115008];
__device__ int g_OFF[115008];
__device__ int g_BSUM[128];
__device__ int2 g_ELIST[1500000];       // (edge, src)

#define CNT_OFS 0
#define CUR_OFS 115008

__device__ __forceinline__ float4 ld_half4(const __half* p) {
    uint2 u = *(const uint2*)p;
    __half2 a = *(__half2*)&u.x, b = *(__half2*)&u.y;
    float2 fa = __half22float2(a), fb = __half22float2(b);
    return make_float4(fa.x, fa.y, fb.x, fb.y);
}
__device__ __forceinline__ void st_half4(__half* p, float4 v) {
    __half2 a = __floats2half2_rn(v.x, v.y);
    __half2 b = __floats2half2_rn(v.z, v.w);
    uint2 u;
    u.x = *(uint32_t*)&a; u.y = *(uint32_t*)&b;
    *(uint2*)p = u;
}

__device__ __forceinline__ void split_pack(float4 v, uint2& hu, uint2& lu) {
    __nv_bfloat16 hx = __float2bfloat16(v.x), hy = __float2bfloat16(v.y);
    __nv_bfloat16 hz = __float2bfloat16(v.z), hw = __float2bfloat16(v.w);
    hu.x = ((uint32_t)__bfloat16_as_ushort(hy) << 16) | __bfloat16_as_ushort(hx);
    hu.y = ((uint32_t)__bfloat16_as_ushort(hw) << 16) | __bfloat16_as_ushort(hz);
    __nv_bfloat16 lx = __float2bfloat16(v.x - __bfloat162float(hx));
    __nv_bfloat16 ly = __float2bfloat16(v.y - __bfloat162float(hy));
    __nv_bfloat16 lz = __float2bfloat16(v.z - __bfloat162float(hz));
    __nv_bfloat16 lw = __float2bfloat16(v.w - __bfloat162float(hw));
    lu.x = ((uint32_t)__bfloat16_as_ushort(ly) << 16) | __bfloat16_as_ushort(lx);
    lu.y = ((uint32_t)__bfloat16_as_ushort(lw) << 16) | __bfloat16_as_ushort(lz);
}

__device__ __forceinline__ uint2 pack_hi(float4 v) {
    __nv_bfloat16 hx = __float2bfloat16(v.x), hy = __float2bfloat16(v.y);
    __nv_bfloat16 hz = __float2bfloat16(v.z), hw = __float2bfloat16(v.w);
    uint2 u;
    u.x = ((uint32_t)__bfloat16_as_ushort(hy) << 16) | __bfloat16_as_ushort(hx);
    u.y = ((uint32_t)__bfloat16_as_ushort(hw) << 16) | __bfloat16_as_ushort(hz);
    return u;
}

#define LDM 136
#define SMEM_BIG  (4 * 128 * LDM * 2)   // Ah, Al, Bh, Bl = 139264 -> 1 blk/SM
#define SMEM_GATE (3 * 128 * LDM * 2)   // A, Bh, Bl = 104448 -> 2 blk/SM

// ---------------- merged prep: weights split + WA + gate table ----------------
struct PrepP {
    const float* w[8];
    const float* Wdst; const float* bdst; const float* attn;
    const float* te; const float* se; const float* Wg; const float* bg;
};
__global__ void prepAll(PrepP P) {
    int b = blockIdx.x;
    if (b < 512) {
        int m = b >> 6;
        int idx = (b & 63) * 256 + threadIdx.x;
        float v = P.w[m][idx];
        __nv_bfloat16 h = __float2bfloat16(v);
        g_WTh[m * 16384 + idx] = h;
        g_WTl[m * 16384 + idx] = __float2bfloat16(v - __bfloat162float(h));
        return;
    }
    if (b < 516) {
        int t = b - 512, k = threadIdx.x;
        if (k >= 128) return;
        const float* W = P.Wdst + t * 16384;
        const float* at = P.attn + t * 128;
        float4 o;
        float* po = &o.x;
#pragma unroll
        for (int h = 0; h < 4; h++) {
            float s = 0.f;
            for (int dh = 0; dh < 32; dh++)
                s = fmaf(W[k * 128 + h * 32 + dh], at[h * 32 + dh], s);
            po[h] = s;
        }
        ((float4*)(g_WA + t * 512))[k] = o;
        if (k < 4) {
            const float* bb = P.bdst + t * 128;
            float s = 0.f;
            for (int dh = 0; dh < 32; dh++) s = fmaf(bb[k * 32 + dh], at[k * 32 + dh], s);
            g_BA[t * 4 + k] = s;
        }
        return;
    }
    {
        int rb = (b - 516) * 2 + (threadIdx.x >> 7);
        int c = threadIdx.x & 127;
        if (rb >= 80) return;
        int a = rb >> 3, bb = rb & 7;
        float s = P.bg[c];
#pragma unroll 8
        for (int j = 0; j < 32; j++) s = fmaf(P.te[a * 32 + j], P.Wg[j * 128 + c], s);
#pragma unroll 8
        for (int j = 0; j < 32; j++) s = fmaf(P.se[bb * 32 + j], P.Wg[(32 + j) * 128 + c], s);
        float g = 1.f / (1.f + expf(-s));
        g_GTAB[rb * 128 + c] = g;
        g_GTA0[rb * 128 + c] = g * P.attn[c];
    }
}

// ---------------- CSR build ----------------
struct EIdx { const int* dst[4]; const int* src[4]; int E[4]; int bofs[4]; int cbase[4]; };

__global__ void histK(EIdx P) {
    int b = blockIdx.x, t = 0;
    while (t + 1 < 4 && b >= P.bofs[t + 1]) t++;
    int e = (b - P.bofs[t]) * 256 + threadIdx.x;
    if (e >= P.E[t]) return;
    atomicAdd(&g_CSR[CNT_OFS + P.cbase[t] + P.dst[t][e]], 1);
}

__global__ void scanA(int N) {
    int base = blockIdx.x * 1024;
    int tid = threadIdx.x, lane = tid & 31, wid = tid >> 5;
    int v[4];
#pragma unroll
    for (int k = 0; k < 4; k++) {
        int i = base + tid * 4 + k;
        v[k] = (i < N) ? g_CSR[CNT_OFS + i] : 0;
    }
    int tsum = v[0] + v[1] + v[2] + v[3];
    int x = tsum;
#pragma unroll
    for (int o = 1; o < 32; o <<= 1) {
        int y = __shfl_up_sync(0xffffffffu, x, o);
        if (lane >= o) x += y;
    }
    __shared__ int ws[8];
    if (lane == 31) ws[wid] = x;
    __syncthreads();
    if (tid == 0) {
        int a = 0;
        for (int w = 0; w < 8; w++) { int tt = ws[w]; ws[w] = a; a += tt; }
        g_BSUM[blockIdx.x] = a;
    }
    __syncthreads();
    int run = x - tsum + ws[wid];
#pragma unroll
    for (int k = 0; k < 4; k++) {
        int i = base + tid * 4 + k;
        if (i < N) g_OFF[i] = run;
        run += v[k];
    }
}

__global__ void scanB(int nb) {
    int tid = threadIdx.x, lane = tid & 31, wid = tid >> 5;
    int v = (tid < nb) ? g_BSUM[tid] : 0;
    int x = v;
#pragma unroll
    for (int o = 1; o < 32; o <<= 1) {
        int y = __shfl_up_sync(0xffffffffu, x, o);
        if (lane >= o) x += y;
    }
    __shared__ int ws[4];
    if (lane == 31) ws[wid] = x;
    __syncthreads();
    int add = 0;
    for (int w = 0; w < wid; w++) add += ws[w];
    if (tid < nb) g_BSUM[tid] = x - v + add;
}

__global__ void scanC(int N) {
    int i = blockIdx.x * 256 + threadIdx.x;
    if (i < N) g_OFF[i] += g_BSUM[i >> 10];
}

__global__ void fillK(EIdx P) {
    int b = blockIdx.x, t = 0;
    while (t + 1 < 4 && b >= P.bofs[t + 1]) t++;
    int e = (b - P.bofs[t]) * 256 + threadIdx.x;
    if (e >= P.E[t]) return;
    int ci = P.cbase[t] + P.dst[t][e];
    int pos = atomicAdd(&g_CSR[CUR_OFS + ci], 1);
    g_ELIST[g_OFF[ci] + pos] = make_int2(e, P.src[t][e]);
}

__device__ __forceinline__ void stage_B(const __nv_bfloat16* gBh, const __nv_bfloat16* gBl,
                                        __nv_bfloat16* Bh, __nv_bfloat16* Bl, int tid)
{
    const uint4* bh = (const uint4*)gBh;
    const uint4* bl = (const uint4*)gBl;
#pragma unroll
    for (int i = 0; i < 8; i++) {
        int idx = tid + 256 * i;
        int row = idx >> 4, c = idx & 15;
        *(uint4*)(Bh + row * LDM + c * 8) = bh[idx];
        *(uint4*)(Bl + row * LDM + c * 8) = bl[idx];
    }
}

typedef wmma::fragment<wmma::accumulator, 16, 16, 16, float> AccFrag;

// 3-pass core over separate Ah/Al buffers: Ah*Bh + Al*Bh + Ah*Bl
__device__ __forceinline__ void wmma_core3(const __nv_bfloat16* Ah, const __nv_bfloat16* Al,
                                           const __nv_bfloat16* Bh, const __nv_bfloat16* Bl,
                                           AccFrag acc[2][4], int wid)
{
    int wr = (wid >> 1) * 32;
    int wc = (wid & 1) * 64;
#pragma unroll
    for (int kk = 0; kk < 8; kk++) {
        wmma::fragment<wmma::matrix_a, 16, 16, 16, __nv_bfloat16, wmma::row_major> ah[2], al[2];
#pragma unroll
        for (int i = 0; i < 2; i++) {
            wmma::load_matrix_sync(ah[i], Ah + (wr + i * 16) * LDM + kk * 16, LDM);
            wmma::load_matrix_sync(al[i], Al + (wr + i * 16) * LDM + kk * 16, LDM);
        }
#pragma unroll
        for (int j = 0; j < 4; j++) {
            wmma::fragment<wmma::matrix_b, 16, 16, 16, __nv_bfloat16, wmma::row_major> bh, bl;
            wmma::load_matrix_sync(bh, Bh + (kk * 16) * LDM + wc + j * 16, LDM);
            wmma::load_matrix_sync(bl, Bl + (kk * 16) * LDM + wc + j * 16, LDM);
#pragma unroll
            for (int i = 0; i < 2; i++) {
                wmma::mma_sync(acc[i][j], ah[i], bh, acc[i][j]);
                wmma::mma_sync(acc[i][j], al[i], bh, acc[i][j]);
                wmma::mma_sync(acc[i][j], ah[i], bl, acc[i][j]);
            }
        }
    }
}

__device__ __forceinline__ void store_acc(AccFrag acc[2][4], float* Cs, int wid) {
    int wr = (wid >> 1) * 32;
    int wc = (wid & 1) * 64;
#pragma unroll
    for (int i = 0; i < 2; i++)
#pragma unroll
        for (int j = 0; j < 4; j++)
            wmma::store_matrix_sync(Cs + (wr + i * 16) * 128 + wc + j * 16,
                                    acc[i][j], 128, wmma::mem_row_major);
}

// ---------------- mm_big: 4-buffer, 1 blk/SM. Y = (X [+X2]) @ W + b ----------------
// Optional fused AS epilogue: AS[r,h] = sum_c Y[r,c]*attnRow[c]
struct SegB { const float* X; const float* X2;
              const __nv_bfloat16* Bh; const __nv_bfloat16* Bl;
              const float* bias; void* Y;
              float* ASout; const float* attnRow;
              int nrows; int tofs; int hout; };
struct SegsB { SegB s[4]; int nseg; };

__global__ void __launch_bounds__(256, 1) mm_big(SegsB P) {
    extern __shared__ char sm[];
    __nv_bfloat16* Ah = (__nv_bfloat16*)sm;
    __nv_bfloat16* Al = Ah + 128 * LDM;
    __nv_bfloat16* Bh = Al + 128 * LDM;
    __nv_bfloat16* Bl = Bh + 128 * LDM;
    float* Cs = (float*)sm;                 // 64KB, aliases Ah+Al
    int b = blockIdx.x, si = 0;
    while (si + 1 < P.nseg && b >= P.s[si + 1].tofs) si++;
    SegB sg = P.s[si];
    int r0 = (b - sg.tofs) * 128;
    int tid = threadIdx.x, wid = tid >> 5, lane = tid & 31;
#pragma unroll 4
    for (int i = 0; i < 16; i++) {
        int idx = tid + 256 * i;
        int row = idx >> 5, c4 = idx & 31, gr = r0 + row;
        float4 v = make_float4(0.f, 0.f, 0.f, 0.f);
        if (gr < sg.nrows) {
            v = ((const float4*)sg.X)[(size_t)gr * 32 + c4];
            if (sg.X2) {
                float4 c = ((const float4*)sg.X2)[(size_t)gr * 32 + c4];
                v.x += c.x; v.y += c.y; v.z += c.z; v.w += c.w;
            }
        }
        uint2 hu, lu;
        split_pack(v, hu, lu);
        *(uint2*)(Ah + row * LDM + c4 * 4) = hu;
        *(uint2*)(Al + row * LDM + c4 * 4) = lu;
    }
    stage_B(sg.Bh, sg.Bl, Bh, Bl, tid);
    __syncthreads();
    AccFrag acc[2][4];
#pragma unroll
    for (int i = 0; i < 2; i++)
#pragma unroll
        for (int j = 0; j < 4; j++) wmma::fill_fragment(acc[i][j], 0.f);
    wmma_core3(Ah, Al, Bh, Bl, acc, wid);
    __syncthreads();
    store_acc(acc, Cs, wid);
    __syncthreads();
    float4 at4 = make_float4(0.f, 0.f, 0.f, 0.f);
    if (sg.ASout) at4 = ((const float4*)sg.attnRow)[lane];
#pragma unroll 4
    for (int i = 0; i < 16; i++) {
        int idx = tid + 256 * i;
        int row = idx >> 5, c4 = idx & 31, gr = r0 + row;   // c4 == lane
        if (gr < sg.nrows) {
            float4 v = ((float4*)Cs)[idx];
            float4 bb = ((const float4*)sg.bias)[c4];
            v.x += bb.x; v.y += bb.y; v.z += bb.z; v.w += bb.w;
            if (sg.hout)
                st_half4((__half*)sg.Y + (size_t)gr * 128 + c4 * 4, v);
            else
                ((float4*)sg.Y)[(size_t)gr * 32 + c4] = v;
            if (sg.ASout) {
                float p = v.x * at4.x + v.y * at4.y + v.z * at4.z + v.w * at4.w;
                p += __shfl_xor_sync(0xffffffffu, p, 4);
                p += __shfl_xor_sync(0xffffffffu, p, 2);
                p += __shfl_xor_sync(0xffffffffu, p, 1);
                if ((lane & 7) == 0) sg.ASout[gr * 4 + (lane >> 3)] = p;
            }
        }
    }
}

// ---------------- mm_gateK: 3-buffer, 2 blk/SM, single-pass hi A ----------------
__global__ void __launch_bounds__(256, 2) mm_gateK(
    const float* __restrict__ cp, const float* __restrict__ W1, const float* __restrict__ b1,
    const __nv_bfloat16* __restrict__ W2h, const __nv_bfloat16* __restrict__ W2l,
    const float* __restrict__ b2, __half* __restrict__ G, int E)
{
    extern __shared__ char sm[];
    __nv_bfloat16* A  = (__nv_bfloat16*)sm;
    __nv_bfloat16* Bh = A + 128 * LDM;
    __nv_bfloat16* Bl = Bh + 128 * LDM;
    float* Cs = (float*)sm;
    int r0 = blockIdx.x * 128;
    int tid = threadIdx.x, wid = tid >> 5;
    stage_B(W2h, W2l, Bh, Bl, tid);
#pragma unroll 4
    for (int i = 0; i < 16; i++) {
        int idx = tid + 256 * i;
        int row = idx >> 5, c4 = idx & 31, ge = r0 + row;
        float4 h4 = make_float4(0.f, 0.f, 0.f, 0.f);
        if (ge < E) {
            float x0 = cp[ge * 3 + 0], x1 = cp[ge * 3 + 1], x2 = cp[ge * 3 + 2];
            float4 w0 = ((const float4*)W1)[c4];
            float4 w1 = ((const float4*)(W1 + 128))[c4];
            float4 w2 = ((const float4*)(W1 + 256))[c4];
            float4 bb = ((const float4*)b1)[c4];
            h4.x = fmaf(x0, w0.x, fmaf(x1, w1.x, fmaf(x2, w2.x, bb.x)));
            h4.y = fmaf(x0, w0.y, fmaf(x1, w1.y, fmaf(x2, w2.y, bb.y)));
            h4.z = fmaf(x0, w0.z, fmaf(x1, w1.z, fmaf(x2, w2.z, bb.z)));
            h4.w = fmaf(x0, w0.w, fmaf(x1, w1.w, fmaf(x2, w2.w, bb.w)));
            h4.x = 0.5f * h4.x * (1.f + erff(h4.x * 0.70710678118654752f));
            h4.y = 0.5f * h4.y * (1.f + erff(h4.y * 0.70710678118654752f));
            h4.z = 0.5f * h4.z * (1.f + erff(h4.z * 0.70710678118654752f));
            h4.w = 0.5f * h4.w * (1.f + erff(h4.w * 0.70710678118654752f));
        }
        *(uint2*)(A + row * LDM + c4 * 4) = pack_hi(h4);
    }
    __syncthreads();
    AccFrag acc[2][4];
#pragma unroll
    for (int i = 0; i < 2; i++)
#pragma unroll
        for (int j = 0; j < 4; j++) wmma::fill_fragment(acc[i][j], 0.f);
    // single A pass against Bh and Bl
    {
        int wr = (wid >> 1) * 32, wc = (wid & 1) * 64;
#pragma unroll
        for (int kk = 0; kk < 8; kk++) {
            wmma::fragment<wmma::matrix_a, 16, 16, 16, __nv_bfloat16, wmma::row_major> ah[2];
#pragma unroll
            for (int i = 0; i < 2; i++)
                wmma::load_matrix_sync(ah[i], A + (wr + i * 16) * LDM + kk * 16, LDM);
#pragma unroll
            for (int j = 0; j < 4; j++) {
                wmma::fragment<wmma::matrix_b, 16, 16, 16, __nv_bfloat16, wmma::row_major> bh, bl;
                wmma::load_matrix_sync(bh, Bh + (kk * 16) * LDM + wc + j * 16, LDM);
                wmma::load_matrix_sync(bl, Bl + (kk * 16) * LDM + wc + j * 16, LDM);
#pragma unroll
                for (int i = 0; i < 2; i++) {
                    wmma::mma_sync(acc[i][j], ah[i], bh, acc[i][j]);
                    wmma::mma_sync(acc[i][j], ah[i], bl, acc[i][j]);
                }
            }
        }
    }
    __syncthreads();
    store_acc(acc, Cs, wid);
    __syncthreads();
#pragma unroll 4
    for (int i = 0; i < 16; i++) {
        int idx = tid + 256 * i;
        int row = idx >> 5, c4 = idx & 31, ge = r0 + row;
        if (ge < E) {
            float4 v = ((float4*)Cs)[idx];
            float4 bb = ((const float4*)b2)[c4];
            float4 o;
            o.x = 1.f / (1.f + expf(-(v.x + bb.x)));
            o.y = 1.f / (1.f + expf(-(v.y + bb.y)));
            o.z = 1.f / (1.f + expf(-(v.z + bb.z)));
            o.w = 1.f / (1.f + expf(-(v.w + bb.w)));
            st_half4(G + (size_t)ge * 128 + c4 * 4, o);
        }
    }
}

// ---------------- AD-only kernel ----------------
struct AdP { const float* x[4]; int n[4]; int bofs[4]; };
__global__ void adK_f(AdP P) {
    int b = blockIdx.x, t = 0;
    while (t + 1 < 4 && b >= P.bofs[t + 1]) t++;
    int r = (b - P.bofs[t]) * 8 + (threadIdx.x >> 5);
    if (r >= P.n[t]) return;
    int lane = threadIdx.x & 31;
    float4 xv = ((const float4*)(P.x[t] + (size_t)r * 128))[lane];
    const float4* W4 = (const float4*)(g_WA + t * 512);
    float4 a0 = W4[4 * lane], a1 = W4[4 * lane + 1], a2 = W4[4 * lane + 2], a3 = W4[4 * lane + 3];
    float p0 = xv.x * a0.x + xv.y * a1.x + xv.z * a2.x + xv.w * a3.x;
    float p1 = xv.x * a0.y + xv.y * a1.y + xv.z * a2.y + xv.w * a3.y;
    float p2 = xv.x * a0.z + xv.y * a1.z + xv.z * a2.z + xv.w * a3.z;
    float p3 = xv.x * a0.w + xv.y * a1.w + xv.z * a2.w + xv.w * a3.w;
#pragma unroll
    for (int m = 16; m; m >>= 1) {
        p0 += __shfl_xor_sync(0xffffffffu, p0, m);
        p1 += __shfl_xor_sync(0xffffffffu, p1, m);
        p2 += __shfl_xor_sync(0xffffffffu, p2, m);
        p3 += __shfl_xor_sync(0xffffffffu, p3, m);
    }
    if (lane == 0)
        ((float4*)(g_AD + t * 200000))[r] =
            make_float4(p0 + g_BA[t * 4], p1 + g_BA[t * 4 + 1],
                        p2 + g_BA[t * 4 + 2], p3 + g_BA[t * 4 + 3]);
}

// ---------------- gather aggregation ----------------
struct AggP {
    const __half* HS[4];
    const float* AS[4];
    const float* AD[4];
    float* acc[4];
    const int* cg;
    const __half* G2;
    const float* attn2;
    int Nd[4]; int bofs[4]; int cbase[4]; int kind[4];
};

__global__ void __launch_bounds__(256) aggK(AggP P) {
    int b = blockIdx.x, t = 0;
    while (t + 1 < 4 && b >= P.bofs[t + 1]) t++;
    int d = (b - P.bofs[t]) * 8 + (threadIdx.x >> 5);
    if (d >= P.Nd[t]) return;
    int lane = threadIdx.x & 31, h = lane >> 3;
    int ci = P.cbase[t] + d;
    int start = g_OFF[ci], len = g_CSR[CNT_OFS + ci];
    int kind = P.kind[t];
    float adh = P.AD[t][(size_t)d * 4 + h];
    const __half* HS = P.HS[t];
    float4 accv = make_float4(0.f, 0.f, 0.f, 0.f);
    float ehs = 0.f;
    if (len == 0) {
        ((float4*)(P.acc[t] + (size_t)d * 128))[lane] = accv;
        return;
    }
    int2 es = g_ELIST[start];
    float4 hs = ld_half4(HS + (size_t)es.y * 128 + lane * 4);
    int2 cgv = make_int2(0, 0);
    float4 gx = make_float4(0.f, 0.f, 0.f, 0.f);
    if (kind == 0) cgv = *(const int2*)(P.cg + 2 * es.x);
    else if (kind == 2) gx = ld_half4(P.G2 + (size_t)es.x * 128 + lane * 4);
    for (int i = 0; i < len; i++) {
        int2 es_c = es;
        float4 hs_c = hs;
        int2 cg_c = cgv;
        float4 g_c = gx;
        if (i + 1 < len) {
            es = g_ELIST[start + i + 1];
            hs = ld_half4(HS + (size_t)es.y * 128 + lane * 4);
            if (kind == 0) cgv = *(const int2*)(P.cg + 2 * es.x);
            else if (kind == 2) gx = ld_half4(P.G2 + (size_t)es.x * 128 + lane * 4);
        }
        float4 msg;
        float eh;
        if (kind == 1) {
            msg = hs_c;
            float l = P.AS[t][es_c.y * 4 + h] + adh;
            eh = expf(l > 0.f ? l : 0.2f * l);
        } else {
            float p;
            if (kind == 0) {
                int comb = cg_c.x * 8 + cg_c.y;
                float4 g = ((const float4*)(g_GTAB + comb * 128))[lane];
                float4 ga = ((const float4*)(g_GTA0 + comb * 128))[lane];
                msg = make_float4(hs_c.x * g.x, hs_c.y * g.y, hs_c.z * g.z, hs_c.w * g.w);
                p = hs_c.x * ga.x + hs_c.y * ga.y + hs_c.z * ga.z + hs_c.w * ga.w;
            } else {
                float4 at = ((const float4*)P.attn2)[lane];
                msg = make_float4(hs_c.x * g_c.x, hs_c.y * g_c.y, hs_c.z * g_c.z, hs_c.w * g_c.w);
                p = msg.x * at.x + msg.y * at.y + msg.z * at.z + msg.w * at.w;
            }
            p += __shfl_xor_sync(0xffffffffu, p, 4);
            p += __shfl_xor_sync(0xffffffffu, p, 2);
            p += __shfl_xor_sync(0xffffffffu, p, 1);
            float l = p + adh;
            eh = expf(l > 0.f ? l : 0.2f * l);
        }
        accv.x = fmaf(eh, msg.x, accv.x);
        accv.y = fmaf(eh, msg.y, accv.y);
        accv.z = fmaf(eh, msg.z, accv.z);
        accv.w = fmaf(eh, msg.w, accv.w);
        ehs += eh;
    }
    float inv = (ehs > 0.f) ? 1.f / ehs : 0.f;
    ((float4*)(P.acc[t] + (size_t)d * 128))[lane] =
        make_float4(accv.x * inv, accv.y * inv, accv.z * inv, accv.w * inv);
}

__global__ void biasfill(float* __restrict__ out, const float* __restrict__ b, int n)
{
    int i = blockIdx.x * blockDim.x + threadIdx.x;
    if (i < n * 128) out[i] = b[i & 127];
}

// ---------------- launch ----------------
extern "C" void kernel_launch(void* const* d_in, const int* in_sizes, int n_in,
                              void* d_out, int out_size)
{
    int iWsrc, ibsrc, iWdst, ibdst, iattn, itemb, isemb, iWg, ibg, iW1c, ib1c,
        iW2c, ib2c, iWout, ibout, icp, icg;
    int isrc[4], idst[4];
    if (in_sizes[4] == 65536) {            // layout A
        iWsrc = 4; ibsrc = 5; iWdst = 6; ibdst = 7; iattn = 8; itemb = 9; isemb = 10;
        iWg = 11; ibg = 12; iW1c = 13; ib1c = 14; iW2c = 15; ib2c = 16;
        iWout = 17; ibout = 18; icp = 19;
        isrc[0] = 20; idst[0] = 21; isrc[1] = 22; idst[1] = 23;
        isrc[2] = 24; idst[2] = 25; isrc[3] = 26; idst[3] = 27; icg = 28;
    } else {                               // layout B
        isrc[0] = 4; idst[0] = 5; isrc[1] = 6; idst[1] = 7;
        isrc[2] = 8; idst[2] = 9; isrc[3] = 10; idst[3] = 11;
        icg = 12; icp = 13;
        iWsrc = 14; ibsrc = 15; iWdst = 16; ibdst = 17; iattn = 18;
        itemb = 19; isemb = 20; iWg = 21; ibg = 22; iW1c = 23; ib1c = 24;
        iW2c = 25; ib2c = 26; iWout = 27; ibout = 28;
    }

    const float* x[4]  = {(const float*)d_in[0], (const float*)d_in[1],
                          (const float*)d_in[2], (const float*)d_in[3]};
    const float* Wsrc  = (const float*)d_in[iWsrc];
    const float* bsrc  = (const float*)d_in[ibsrc];
    const float* Wdst  = (const float*)d_in[iWdst];
    const float* bdst  = (const float*)d_in[ibdst];
    const float* attn  = (const float*)d_in[iattn];
    const float* temb  = (const float*)d_in[itemb];
    const float* semb  = (const float*)d_in[isemb];
    const float* Wg    = (const float*)d_in[iWg];
    const float* bg    = (const float*)d_in[ibg];
    const float* W1c   = (const float*)d_in[iW1c];
    const float* b1c   = (const float*)d_in[ib1c];
    const float* W2c   = (const float*)d_in[iW2c];
    const float* b2c   = (const float*)d_in[ib2c];
    const float* Wout  = (const float*)d_in[iWout];
    const float* bout  = (const float*)d_in[ibout];
    const float* cp    = (const float*)d_in[icp];
    const int* srcp[4] = {(const int*)d_in[isrc[0]], (const int*)d_in[isrc[1]],
                          (const int*)d_in[isrc[2]], (const int*)d_in[isrc[3]]};
    const int* dstp[4] = {(const int*)d_in[idst[0]], (const int*)d_in[idst[1]],
                          (const int*)d_in[idst[2]], (const int*)d_in[idst[3]]};
    const int* cg      = (const int*)d_in[icg];
    float* out = (float*)d_out;

    int Nn[4] = {in_sizes[0] / 128, in_sizes[1] / 128, in_sizes[2] / 128, in_sizes[3] / 128};
    int Ee[4] = {in_sizes[isrc[0]], in_sizes[isrc[1]], in_sizes[isrc[2]], in_sizes[isrc[3]]};
    int sidx[4] = {0, 1, 0, 2};
    int didx[4] = {1, 0, 3, 1};

    float *ACC, *AS, *AD;
    __half *Hh, *G2h;
    __nv_bfloat16 *WTh, *WTl;
    int *CSRp;
    cudaGetSymbolAddress((void**)&Hh, g_Hh);
    cudaGetSymbolAddress((void**)&G2h, g_G2h);
    cudaGetSymbolAddress((void**)&ACC, g_ACC);
    cudaGetSymbolAddress((void**)&AS, g_AS);
    cudaGetSymbolAddress((void**)&AD, g_AD);
    cudaGetSymbolAddress((void**)&WTh, g_WTh);
    cudaGetSymbolAddress((void**)&WTl, g_WTl);
    cudaGetSymbolAddress((void**)&CSRp, g_CSR);

    cudaFuncSetAttribute(mm_big, cudaFuncAttributeMaxDynamicSharedMemorySize, SMEM_BIG);
    cudaFuncSetAttribute(mm_gateK, cudaFuncAttributeMaxDynamicSharedMemorySize, SMEM_GATE);

    size_t hofs[4] = {0, 50000, 80000, 130000};
    __half* HSp[4] = {Hh, Hh + hofs[1] * 128, Hh + hofs[2] * 128, Hh + hofs[3] * 128};
    float* AD_t[4]  = {AD, AD + 200000, AD + 400000, AD + 600000};
    int Ndst[4] = {Nn[didx[0]], Nn[didx[1]], Nn[didx[2]], Nn[didx[3]]};
    int cbase[4];
    cbase[0] = 0;
    for (int t = 1; t < 4; t++) cbase[t] = cbase[t - 1] + Ndst[t - 1];
    int NTOT = cbase[3] + Ndst[3];
    float* accT[4];
    for (int t = 0; t < 4; t++) accT[t] = ACC + (size_t)cbase[t] * 128;

    // ---- CSR build (one memset for counts + cursors) ----
    cudaMemsetAsync(CSRp, 0, 2 * 115008 * sizeof(int));
    EIdx EI;
    int ebo = 0;
    for (int t = 0; t < 4; t++) {
        EI.dst[t] = dstp[t];
        EI.src[t] = srcp[t];
        EI.E[t] = Ee[t];
        EI.cbase[t] = cbase[t];
        EI.bofs[t] = ebo;
        ebo += (Ee[t] + 255) / 256;
    }
    histK<<<ebo, 256>>>(EI);
    int nb = (NTOT + 1023) / 1024;
    scanA<<<nb, 256>>>(NTOT);
    scanB<<<1, 128>>>(nb);
    scanC<<<(NTOT + 255) / 256, 256>>>(NTOT);
    fillK<<<ebo, 256>>>(EI);

    // ---- merged prep ----
    PrepP PR;
    PR.w[0] = Wsrc;             PR.w[1] = Wsrc + 16384;
    PR.w[2] = Wsrc + 2 * 16384; PR.w[3] = Wsrc + 3 * 16384;
    PR.w[4] = Wout;             PR.w[5] = Wout + 16384;
    PR.w[6] = Wout + 3 * 16384; PR.w[7] = W2c;
    PR.Wdst = Wdst; PR.bdst = bdst; PR.attn = attn;
    PR.te = temb; PR.se = semb; PR.Wg = Wg; PR.bg = bg;
    prepAll<<<556, 256>>>(PR);

    // ---- AD (needs only prepAll) ----
    AdP PA;
    int abo = 0;
    for (int t = 0; t < 4; t++) {
        PA.x[t] = x[didx[t]];
        PA.n[t] = Ndst[t];
        PA.bofs[t] = abo;
        abo += (Ndst[t] + 7) / 8;
    }
    adK_f<<<abo, 256>>>(PA);

    // ---- transforms GEMM (4-buffer) with fused AS for t1/t3 ----
    SegsB T;
    T.nseg = 4;
    int tcum = 0;
    for (int t = 0; t < 4; t++) {
        int ns = Nn[sidx[t]];
        T.s[t].X = x[sidx[t]];
        T.s[t].X2 = nullptr;
        T.s[t].Bh = WTh + t * 16384;
        T.s[t].Bl = WTl + t * 16384;
        T.s[t].bias = bsrc + t * 128;
        T.s[t].Y = HSp[t];
        T.s[t].ASout = nullptr; T.s[t].attnRow = nullptr;
        T.s[t].nrows = ns;
        T.s[t].tofs = tcum;
        T.s[t].hout = 1;
        tcum += (ns + 127) / 128;
    }
    T.s[1].ASout = AS;            T.s[1].attnRow = attn + 128;
    T.s[3].ASout = AS + 200000;   T.s[3].attnRow = attn + 3 * 128;
    mm_big<<<tcum, 256, SMEM_BIG>>>(T);

    // ---- gate GEMM (3-buffer, 2/SM, single-pass) ----
    mm_gateK<<<(Ee[2] + 127) / 128, 256, SMEM_GATE>>>(cp, W1c, b1c,
        WTh + 7 * 16384, WTl + 7 * 16384, b2c, G2h, Ee[2]);

    // ---- gather aggregation ----
    AggP PG;
    PG.cg = cg; PG.G2 = G2h; PG.attn2 = attn + 2 * 128;
    int kindE[4] = {0, 1, 2, 1};
    const float* AS_t[4] = {nullptr, AS, nullptr, AS + 200000};
    int gbo = 0;
    for (int t = 0; t < 4; t++) {
        PG.HS[t] = HSp[t];
        PG.AS[t] = AS_t[t]; PG.AD[t] = AD_t[t];
        PG.acc[t] = accT[t];
        PG.Nd[t] = Ndst[t]; PG.cbase[t] = cbase[t]; PG.kind[t] = kindE[t];
        PG.bofs[t] = gbo;
        gbo += (Ndst[t] + 7) / 8;
    }
    aggK<<<gbo, 256>>>(PG);

    // ---- output GEMMs (4-buffer) ----
    float* o_chem = out;
    float* o_gene = o_chem + (size_t)Nn[0] * 128;
    float* o_dis  = o_gene + (size_t)Nn[1] * 128;
    float* o_path = o_dis + (size_t)Nn[2] * 128;
    SegsB O;
    O.nseg = 3;
    int b0 = (Nn[0] + 127) / 128;
    int b1 = (Nn[1] + 127) / 128;
    int b2 = (Nn[3] + 127) / 128;
    O.s[0] = {accT[1], nullptr, WTh + 4 * 16384, WTl + 4 * 16384, bout,
              o_chem, nullptr, nullptr, Nn[0], 0,       0};
    O.s[1] = {accT[0], accT[3], WTh + 5 * 16384, WTl + 5 * 16384, bout + 128,
              o_gene, nullptr, nullptr, Nn[1], b0,      0};
    O.s[2] = {accT[2], nullptr, WTh + 6 * 16384, WTl + 6 * 16384, bout + 384,
              o_path, nullptr, nullptr, Nn[3], b0 + b1, 0};
    mm_big<<<b0 + b1 + b2, 256, SMEM_BIG>>>(O);
    biasfill<<<(Nn[2] * 128 + 255) / 256, 256>>>(o_dis, bout + 256, Nn[2]);
}